// round 2
// baseline (speedup 1.0000x reference)
#include <cuda_runtime.h>

#define NN 8192
#define EE 65536
#define GG 16
#define NELEM 10
#define CC 64

// ---------------- persistent device scratch (no allocs allowed) ----------------
__device__ float d_vec[EE*3];
__device__ float d_r[EE];
__device__ int   d_act[EE];
__device__ float d_Y[EE*16];
__device__ float d_Rb[EE*8];
__device__ float d_w[2][EE*64];
__device__ float d_A[2][NN*1024];
__device__ float d_Bf[NN*256];
__device__ float d_h0[NN*64];
__device__ float d_h1[NN*64];
__device__ float d_h2[NN*64];
__device__ float d_dh1[NN*64];
__device__ float d_dB0[NN*256];
__device__ float d_dB1e[NELEM*256];
__device__ float d_dY[EE*16];
__device__ float d_dR[EE*8];
__device__ float d_gpos[NN*3];
__device__ float d_eng[GG];
__device__ int d_elem[NN];
__device__ int d_deg[NN];
__device__ int d_rowptr[NN+1];
__device__ int d_cursor[NN];
__device__ int d_perm[EE];

// ---------------- setup ----------------
__global__ void k_prep(const float* __restrict__ attrs){
  int n = blockIdx.x*blockDim.x + threadIdx.x;
  if (n < GG) d_eng[n] = 0.f;
  if (n >= NN) return;
  int el = 0;
  const float* a = attrs + n*NELEM;
  #pragma unroll
  for (int e = 1; e < NELEM; e++) if (a[e] > 0.5f) el = e;
  d_elem[n] = el;
  d_deg[n]  = 0;
  d_gpos[3*n] = 0.f; d_gpos[3*n+1] = 0.f; d_gpos[3*n+2] = 0.f;
}

__global__ void k_zero_dh1(){
  int i = blockIdx.x*blockDim.x + threadIdx.x;
  if (i < NN*64) d_dh1[i] = 0.f;
}

__global__ void k_hist(const int* __restrict__ ei){
  int e = blockIdx.x*blockDim.x + threadIdx.x;
  if (e < EE) atomicAdd(&d_deg[ei[EE+e]], 1);
}

__global__ void k_scan(){
  __shared__ int sh[1024];
  int t = threadIdx.x;
  int base = t*8;
  int loc[8]; int s = 0;
  #pragma unroll
  for (int i = 0; i < 8; i++){ loc[i] = s; s += d_deg[base+i]; }
  sh[t] = s; __syncthreads();
  for (int off = 1; off < 1024; off <<= 1){
    int v = (t >= off) ? sh[t-off] : 0;
    __syncthreads();
    sh[t] += v;
    __syncthreads();
  }
  int excl = sh[t] - s;
  #pragma unroll
  for (int i = 0; i < 8; i++){ int v = excl + loc[i]; d_rowptr[base+i] = v; d_cursor[base+i] = v; }
  if (t == 1023) d_rowptr[NN] = sh[1023];
}

__global__ void k_fill(const int* __restrict__ ei){
  int e = blockIdx.x*blockDim.x + threadIdx.x;
  if (e >= EE) return;
  int p = atomicAdd(&d_cursor[ei[EE+e]], 1);
  d_perm[p] = e;
}

// ---------------- geometry: vec, r, Y(16), R(8), active ----------------
__global__ void k_geom(const float* __restrict__ pos, const float* __restrict__ shifts,
                       const int* __restrict__ ei){
  int e = blockIdx.x*blockDim.x + threadIdx.x;
  if (e >= EE) return;
  int s = ei[e], n = ei[EE+e];
  float vx = pos[3*n]   - pos[3*s]   + shifts[3*e];
  float vy = pos[3*n+1] - pos[3*s+1] + shifts[3*e+1];
  float vz = pos[3*n+2] - pos[3*s+2] + shifts[3*e+2];
  float r = sqrtf(vx*vx + vy*vy + vz*vz + 1e-9f);
  d_vec[3*e] = vx; d_vec[3*e+1] = vy; d_vec[3*e+2] = vz;
  d_r[e] = r;
  float inv = 1.f/r;
  float x = vx*inv, y = vy*inv, z = vz*inv;
  float x2 = x*x, y2 = y*y, z2 = z*z;
  float* Y = d_Y + e*16;
  Y[0]  = 0.28209479177387814f;
  Y[1]  = 0.4886025119029199f*y;
  Y[2]  = 0.4886025119029199f*z;
  Y[3]  = 0.4886025119029199f*x;
  Y[4]  = 1.0925484305920792f*x*y;
  Y[5]  = 1.0925484305920792f*y*z;
  Y[6]  = 0.31539156525252005f*(3.f*z2 - 1.f);
  Y[7]  = 1.0925484305920792f*x*z;
  Y[8]  = 0.5462742152960396f*(x2 - y2);
  Y[9]  = 0.5900435899266435f*y*(3.f*x2 - y2);
  Y[10] = 2.890611442640554f*x*y*z;
  Y[11] = 0.4570457994644658f*y*(5.f*z2 - 1.f);
  Y[12] = 0.3731763325901154f*z*(5.f*z2 - 3.f);
  Y[13] = 0.4570457994644658f*x*(5.f*z2 - 1.f);
  Y[14] = 1.445305721320277f*z*(x2 - y2);
  Y[15] = 0.5900435899266435f*x*(x2 - 3.f*y2);
  float u = r*0.2f;
  int act = (u < 1.f);
  d_act[e] = act;
  float* R = d_Rb + e*8;
  if (act){
    float u2 = u*u; float u4 = u2*u2;
    float cut = 1.f + u4*u*(-21.f + u*(35.f - 15.f*u));
    float pref = 0.6324555320336759f * inv;
    #pragma unroll
    for (int b = 1; b <= 8; b++) R[b-1] = pref * sinpif((float)b*u) * cut;
  } else {
    #pragma unroll
    for (int b = 0; b < 8; b++) R[b] = 0.f;
  }
}

// ---------------- h0 = one_hot @ W_embed ----------------
__global__ void k_h0(const float* __restrict__ Wemb){
  int i = blockIdx.x*blockDim.x + threadIdx.x;
  int n = i >> 6, c = i & 63;
  d_h0[i] = Wemb[d_elem[n]*64 + c];
}

// ---------------- per-edge radial weights w = R @ W_rad[layer] ----------------
__global__ void k_edge_w(int layer, const float* __restrict__ Wrad){
  int idx = blockIdx.x*blockDim.x + threadIdx.x;
  if (idx >= EE*64) return;
  int e = idx >> 6, c = idx & 63;
  if (!d_act[e]) return;
  const float* R = d_Rb + e*8;
  float acc = 0.f;
  #pragma unroll
  for (int b = 0; b < 8; b++) acc += R[b]*Wrad[b*64 + c];
  d_w[layer][e*64 + c] = acc;
}

// ---------------- CSR gather: A[n,16,64] and B[n,256] ----------------
__global__ void k_gather(int layer, const int* __restrict__ ei){
  int n = blockIdx.x*4 + (threadIdx.x >> 5);
  int lane = threadIdx.x & 31;
  const float* __restrict__ h_in = (layer == 0) ? d_h0 : d_h1;
  float a0[16], a1[16];
  #pragma unroll
  for (int i = 0; i < 16; i++){ a0[i] = 0.f; a1[i] = 0.f; }
  int beg = d_rowptr[n], end = d_rowptr[n+1];
  for (int j = beg; j < end; j++){
    int e = d_perm[j];
    if (!d_act[e]) continue;
    int s = ei[e];
    float wh0 = d_w[layer][e*64 + lane]      * h_in[s*64 + lane];
    float wh1 = d_w[layer][e*64 + 32 + lane] * h_in[s*64 + 32 + lane];
    const float4* Yp = (const float4*)(d_Y + e*16);
    #pragma unroll
    for (int q = 0; q < 4; q++){
      float4 y = Yp[q];
      a0[4*q+0] += wh0*y.x; a1[4*q+0] += wh1*y.x;
      a0[4*q+1] += wh0*y.y; a1[4*q+1] += wh1*y.y;
      a0[4*q+2] += wh0*y.z; a1[4*q+2] += wh1*y.z;
      a0[4*q+3] += wh0*y.w; a1[4*q+3] += wh1*y.w;
    }
  }
  float* A = d_A[layer] + n*1024;
  #pragma unroll
  for (int lm = 0; lm < 16; lm++){ A[lm*64 + lane] = a0[lm]; A[lm*64 + 32 + lane] = a1[lm]; }
  float b0[4] = {0,0,0,0}, b1[4] = {0,0,0,0};
  #pragma unroll
  for (int lm = 0; lm < 16; lm++){
    int l = (lm == 0) ? 0 : (lm < 4) ? 1 : (lm < 9) ? 2 : 3;
    b0[l] += a0[lm]*a0[lm]; b1[l] += a1[lm]*a1[lm];
  }
  #pragma unroll
  for (int l = 0; l < 4; l++){
    d_Bf[n*256 + l*64 + lane]      = b0[l];
    d_Bf[n*256 + l*64 + 32 + lane] = b1[l];
  }
}

// ---------------- h_out[n,c] = B[n,:] @ W_prod[layer][elem[n]] ----------------
__global__ void k_node_h(int layer, const float* __restrict__ Wprod){
  __shared__ float Bs[256];
  int n = blockIdx.x, c = threadIdx.x;
  #pragma unroll
  for (int i = 0; i < 4; i++) Bs[c + i*64] = d_Bf[n*256 + c + i*64];
  __syncthreads();
  const float* W = Wprod + (layer*NELEM + d_elem[n])*16384;
  float acc = 0.f;
  #pragma unroll 8
  for (int f = 0; f < 256; f++) acc += Bs[f]*W[f*64 + c];
  float* h_out = (layer == 0) ? d_h1 : d_h2;
  h_out[n*64 + c] = acc;
}

// ---------------- backward: dB1 per element = Wp[1][el] @ w_read ----------------
__global__ void k_dB1e(const float* __restrict__ Wprod, const float* __restrict__ w_read){
  __shared__ float wr[64];
  int el = blockIdx.x, f = threadIdx.x;
  if (f < 64) wr[f] = w_read[f];
  __syncthreads();
  const float* W = Wprod + (NELEM + el)*16384 + f*64;
  float acc = 0.f;
  #pragma unroll
  for (int c = 0; c < 64; c++) acc += wr[c]*W[c];
  d_dB1e[el*256 + f] = acc;
}

// ---------------- backward: dB0[n] = Wp[0][el] @ dh1[n] ----------------
__global__ void k_dB0(const float* __restrict__ Wprod){
  __shared__ float dh[64];
  int n = blockIdx.x, f = threadIdx.x;
  if (f < 64) dh[f] = d_dh1[n*64 + f];
  __syncthreads();
  const float* W = Wprod + d_elem[n]*16384 + f*64;
  float acc = 0.f;
  #pragma unroll
  for (int c = 0; c < 64; c++) acc += dh[c]*W[c];
  d_dB0[n*256 + f] = acc;
}

// ---------------- backward through one layer's edges ----------------
template<int LAYER>
__global__ void k_edge_bwd(const float* __restrict__ Wrad, const int* __restrict__ ei){
  int e = blockIdx.x*4 + (threadIdx.x >> 5);
  int lane = threadIdx.x & 31;
  if (!d_act[e]) return;
  int s = ei[e], n = ei[EE+e];
  const float* __restrict__ h_in = (LAYER == 0) ? d_h0 : d_h1;
  const float* A  = d_A[LAYER] + n*1024;
  const float* dB = (LAYER == 1) ? (d_dB1e + d_elem[n]*256) : (d_dB0 + n*256);
  float w0 = d_w[LAYER][e*64 + lane], w1 = d_w[LAYER][e*64 + 32 + lane];
  float hv0 = h_in[s*64 + lane],      hv1 = h_in[s*64 + 32 + lane];
  float wh0 = w0*hv0, wh1 = w1*hv1;
  float g0 = 0.f, g1 = 0.f;
  float dy[16];
  #pragma unroll
  for (int lm = 0; lm < 16; lm++){
    int l = (lm == 0) ? 0 : (lm < 4) ? 1 : (lm < 9) ? 2 : 3;
    float dA0 = 2.f*A[lm*64 + lane]      * dB[l*64 + lane];
    float dA1 = 2.f*A[lm*64 + 32 + lane] * dB[l*64 + 32 + lane];
    float y = d_Y[e*16 + lm];
    g0 += dA0*y; g1 += dA1*y;
    float p = dA0*wh0 + dA1*wh1;
    #pragma unroll
    for (int off = 16; off > 0; off >>= 1) p += __shfl_xor_sync(0xffffffffu, p, off);
    dy[lm] = p;
  }
  float t0 = g0*hv0, t1 = g1*hv1;
  float dr[8];
  #pragma unroll
  for (int b = 0; b < 8; b++){
    float p = t0*Wrad[b*64 + lane] + t1*Wrad[b*64 + 32 + lane];
    #pragma unroll
    for (int off = 16; off > 0; off >>= 1) p += __shfl_xor_sync(0xffffffffu, p, off);
    dr[b] = p;
  }
  if (lane == 0){
    if (LAYER == 1){
      #pragma unroll
      for (int lm = 0; lm < 16; lm++) d_dY[e*16 + lm] = dy[lm];
      #pragma unroll
      for (int b = 0; b < 8; b++) d_dR[e*8 + b] = dr[b];
    } else {
      #pragma unroll
      for (int lm = 0; lm < 16; lm++) d_dY[e*16 + lm] += dy[lm];
      #pragma unroll
      for (int b = 0; b < 8; b++) d_dR[e*8 + b] += dr[b];
    }
  }
  if (LAYER == 1){
    atomicAdd(&d_dh1[s*64 + lane],      g0*w0);
    atomicAdd(&d_dh1[s*64 + 32 + lane], g1*w1);
  }
}

// ---------------- backward through geometry (SH + Bessel jacobians) ----------------
__global__ void k_geom_bwd(const int* __restrict__ ei){
  int e = blockIdx.x*blockDim.x + threadIdx.x;
  if (e >= EE) return;
  if (!d_act[e]) return;
  float vx = d_vec[3*e], vy = d_vec[3*e+1], vz = d_vec[3*e+2];
  float r = d_r[e], inv = 1.f/r;
  float x = vx*inv, y = vy*inv, z = vz*inv;
  float x2 = x*x, y2 = y*y, z2 = z*z;
  const float* dY = d_dY + e*16;
  float gx = 0.f, gy = 0.f, gz = 0.f;
  gy += 0.4886025119029199f*dY[1];
  gz += 0.4886025119029199f*dY[2];
  gx += 0.4886025119029199f*dY[3];
  gx += 1.0925484305920792f*y*dY[4];  gy += 1.0925484305920792f*x*dY[4];
  gy += 1.0925484305920792f*z*dY[5];  gz += 1.0925484305920792f*y*dY[5];
  gz += 1.8923493915151203f*z*dY[6];                       // 6*c6
  gx += 1.0925484305920792f*z*dY[7];  gz += 1.0925484305920792f*x*dY[7];
  gx += 1.0925484305920792f*x*dY[8];  gy -= 1.0925484305920792f*y*dY[8];   // 2*c8
  gx += 3.540261539559861f*x*y*dY[9]; gy += 1.7701307697799304f*(x2-y2)*dY[9]; // 6c5, 3c5
  gx += 2.890611442640554f*y*z*dY[10]; gy += 2.890611442640554f*x*z*dY[10]; gz += 2.890611442640554f*x*y*dY[10];
  gy += 0.4570457994644658f*(5.f*z2-1.f)*dY[11]; gz += 4.570457994644658f*y*z*dY[11];
  gz += 0.3731763325901154f*(15.f*z2-3.f)*dY[12];
  gx += 0.4570457994644658f*(5.f*z2-1.f)*dY[13]; gz += 4.570457994644658f*x*z*dY[13];
  gx += 2.890611442640554f*x*z*dY[14]; gy -= 2.890611442640554f*y*z*dY[14]; gz += 1.445305721320277f*(x2-y2)*dY[14];
  gx += 1.7701307697799304f*(x2-y2)*dY[15]; gy -= 3.540261539559861f*x*y*dY[15];
  // radial backward
  float u = r*0.2f;
  float u2 = u*u; float u4 = u2*u2;
  float omu = 1.f - u;
  float cut  = 1.f + u4*u*(-21.f + u*(35.f - 15.f*u));
  float cutp = -105.f*u4*omu*omu;
  const float* dR = d_dR + e*8;
  const float pref = 0.6324555320336759f;
  const float PI_F = 3.14159265358979323846f;
  float drdr = 0.f;
  #pragma unroll
  for (int b = 1; b <= 8; b++){
    float sp, cp;
    sincospif((float)b*u, &sp, &cp);
    float dterm = pref*(((float)b*PI_F*0.2f)*cp*inv - sp*inv*inv)*cut
                + pref*sp*inv*cutp*0.2f;
    drdr += dR[b-1]*dterm;
  }
  float gdv = gx*vx + gy*vy + gz*vz;
  float inv3 = inv*inv*inv;
  float dvx = gx*inv - gdv*vx*inv3 + drdr*vx*inv;
  float dvy = gy*inv - gdv*vy*inv3 + drdr*vy*inv;
  float dvz = gz*inv - gdv*vz*inv3 + drdr*vz*inv;
  int s = ei[e], n = ei[EE+e];
  atomicAdd(&d_gpos[3*n],   dvx); atomicAdd(&d_gpos[3*n+1],  dvy); atomicAdd(&d_gpos[3*n+2],  dvz);
  atomicAdd(&d_gpos[3*s],  -dvx); atomicAdd(&d_gpos[3*s+1], -dvy); atomicAdd(&d_gpos[3*s+2], -dvz);
}

// ---------------- energies ----------------
__global__ void k_energy(const float* __restrict__ w_read, const float* __restrict__ ae,
                         const int* __restrict__ batch){
  __shared__ float part[GG];
  int t = threadIdx.x;
  if (t < GG) part[t] = 0.f;
  __syncthreads();
  int n = blockIdx.x*256 + t;
  const float* h = d_h2 + n*64;
  float acc = 0.f;
  #pragma unroll
  for (int c = 0; c < 64; c++) acc += h[c]*w_read[c];
  acc += ae[d_elem[n]];
  atomicAdd(&part[batch[n]], acc);
  __syncthreads();
  if (t < GG) atomicAdd(&d_eng[t], part[t]);
}

__global__ void k_final(float* __restrict__ out){
  int i = blockIdx.x*blockDim.x + threadIdx.x;
  if (i < GG) out[i] = d_eng[i];
  if (i < NN*3) out[GG + i] = -d_gpos[i];
}

// ---------------- launch ----------------
extern "C" void kernel_launch(void* const* d_in, const int* in_sizes, int n_in,
                              void* d_out, int out_size){
  const float* pos    = (const float*)d_in[0];
  const float* attrs  = (const float*)d_in[1];
  const float* shifts = (const float*)d_in[2];
  const float* Wemb   = (const float*)d_in[3];
  const float* aew    = (const float*)d_in[4];
  const float* Wrad   = (const float*)d_in[5];
  const float* Wprod  = (const float*)d_in[6];
  const float* wread  = (const float*)d_in[7];
  const int*   ei     = (const int*)d_in[8];
  const int*   batch  = (const int*)d_in[9];
  float* out = (float*)d_out;

  k_prep<<<NN/256, 256>>>(attrs);
  k_zero_dh1<<<NN*64/256, 256>>>();
  k_hist<<<EE/256, 256>>>(ei);
  k_scan<<<1, 1024>>>();
  k_fill<<<EE/256, 256>>>(ei);
  k_geom<<<EE/256, 256>>>(pos, shifts, ei);
  k_h0<<<NN*64/256, 256>>>(Wemb);

  // layer 0 forward
  k_edge_w<<<EE*64/256, 256>>>(0, Wrad);
  k_gather<<<NN/4, 128>>>(0, ei);
  k_node_h<<<NN, 64>>>(0, Wprod);
  // layer 1 forward
  k_edge_w<<<EE*64/256, 256>>>(1, Wrad + 8*64);
  k_gather<<<NN/4, 128>>>(1, ei);
  k_node_h<<<NN, 64>>>(1, Wprod);

  k_energy<<<NN/256, 256>>>(wread, aew, batch);

  // backward
  k_dB1e<<<NELEM, 256>>>(Wprod, wread);
  k_edge_bwd<1><<<EE/4, 128>>>(Wrad + 8*64, ei);
  k_dB0<<<NN, 256>>>(Wprod);
  k_edge_bwd<0><<<EE/4, 128>>>(Wrad, ei);
  k_geom_bwd<<<EE/256, 256>>>(ei);

  k_final<<<(NN*3 + 255)/256, 256>>>(out);
}

// round 3
// speedup vs baseline: 2.3767x; 2.3767x over previous
#include <cuda_runtime.h>

#define NN 8192
#define EE 65536
#define GG 16
#define NELEM 10
#define CC 64
#define TILES 128   // 32-node tiles per element; covers up to 4096 nodes/element

// ---------------- persistent device scratch ----------------
__device__ float d_vec[EE*3];
__device__ float d_r[EE];
__device__ int   d_act[EE];
__device__ float d_Y[EE*16];
__device__ float d_Rb[EE*8];
__device__ float d_w[2][EE*64];
__device__ float d_A[2][NN*1024];
__device__ float d_Bf[NN*256];
__device__ float d_h0[NN*64];
__device__ float d_h1[NN*64];
__device__ float d_h2[NN*64];
__device__ float d_dh1[NN*64];
__device__ float d_dB0[NN*256];
__device__ float d_dB1e[NELEM*256];
__device__ float d_dY[EE*16];
__device__ float d_dR[EE*8];
__device__ float d_gpos[NN*3];
__device__ float d_eng[GG];
__device__ int d_elem[NN];
__device__ int d_deg[NN];
__device__ int d_rowptr[NN+1];
__device__ int d_cursor[NN];
__device__ int d_perm[EE];
__device__ int d_elptr[NELEM+1];
__device__ int d_elcur[NELEM];
__device__ int d_nbyel[NN];

// ---------------- setup: zero dh1, elem decode, zero deg/gpos/eng ----------------
__global__ void k_prep(const float* __restrict__ attrs){
  int i = blockIdx.x*blockDim.x + threadIdx.x;   // grid covers NN*64
  d_dh1[i] = 0.f;
  if (i < GG) d_eng[i] = 0.f;
  if (i < NN){
    int el = 0;
    const float* a = attrs + i*NELEM;
    #pragma unroll
    for (int e = 1; e < NELEM; e++) if (a[e] > 0.5f) el = e;
    d_elem[i] = el;
    d_deg[i]  = 0;
    d_gpos[3*i] = 0.f; d_gpos[3*i+1] = 0.f; d_gpos[3*i+2] = 0.f;
  }
}

__global__ void k_hist(const int* __restrict__ ei){
  int e = blockIdx.x*blockDim.x + threadIdx.x;
  if (e < EE) atomicAdd(&d_deg[ei[EE+e]], 1);
}

// ---------------- one-block scan: edge rowptr + element offsets ----------------
__global__ void k_scan(){
  __shared__ int wsum[8];
  __shared__ int elbin[NELEM];
  int t = threadIdx.x;          // 256 threads, 32 nodes each
  int lane = t & 31, w = t >> 5;
  if (t < NELEM) elbin[t] = 0;
  __syncthreads();
  int base = t*32;
  int dg[32];
  const int4* dp = (const int4*)(d_deg + base);
  #pragma unroll
  for (int q = 0; q < 8; q++){
    int4 v = dp[q];
    dg[4*q] = v.x; dg[4*q+1] = v.y; dg[4*q+2] = v.z; dg[4*q+3] = v.w;
  }
  int loc[32]; int s = 0;
  #pragma unroll
  for (int i = 0; i < 32; i++){ loc[i] = s; s += dg[i]; }
  // element histogram
  for (int i = 0; i < 32; i++) atomicAdd(&elbin[d_elem[base+i]], 1);
  // warp inclusive scan of s
  int pref = s;
  #pragma unroll
  for (int off = 1; off < 32; off <<= 1){
    int v = __shfl_up_sync(0xffffffffu, pref, off);
    if (lane >= off) pref += v;
  }
  if (lane == 31) wsum[w] = pref;
  __syncthreads();
  if (t == 0){
    int a = 0;
    #pragma unroll
    for (int k = 0; k < 8; k++){ int tmp = wsum[k]; wsum[k] = a; a += tmp; }
    d_rowptr[NN] = a;
    int b = 0;
    #pragma unroll
    for (int e = 0; e < NELEM; e++){ d_elptr[e] = b; d_elcur[e] = b; b += elbin[e]; }
    d_elptr[NELEM] = b;
  }
  __syncthreads();
  int excl = pref - s + wsum[w];
  #pragma unroll
  for (int i = 0; i < 32; i++){
    int v = excl + loc[i];
    d_rowptr[base+i] = v; d_cursor[base+i] = v;
  }
}

// ---------------- fill CSR perm + node-by-element list ----------------
__global__ void k_fill(const int* __restrict__ ei){
  int idx = blockIdx.x*blockDim.x + threadIdx.x;
  if (idx < EE){
    int p = atomicAdd(&d_cursor[ei[EE+idx]], 1);
    d_perm[p] = idx;
  }
  if (idx < NN){
    int q = atomicAdd(&d_elcur[d_elem[idx]], 1);
    d_nbyel[q] = idx;
  }
}

// ---------------- geometry: vec, r, Y(16), R(8), active ----------------
__global__ void k_geom(const float* __restrict__ pos, const float* __restrict__ shifts,
                       const int* __restrict__ ei){
  int e = blockIdx.x*blockDim.x + threadIdx.x;
  if (e >= EE) return;
  int s = ei[e], n = ei[EE+e];
  float vx = pos[3*n]   - pos[3*s]   + shifts[3*e];
  float vy = pos[3*n+1] - pos[3*s+1] + shifts[3*e+1];
  float vz = pos[3*n+2] - pos[3*s+2] + shifts[3*e+2];
  float r = sqrtf(vx*vx + vy*vy + vz*vz + 1e-9f);
  d_vec[3*e] = vx; d_vec[3*e+1] = vy; d_vec[3*e+2] = vz;
  d_r[e] = r;
  float inv = 1.f/r;
  float x = vx*inv, y = vy*inv, z = vz*inv;
  float x2 = x*x, y2 = y*y, z2 = z*z;
  float* Y = d_Y + e*16;
  Y[0]  = 0.28209479177387814f;
  Y[1]  = 0.4886025119029199f*y;
  Y[2]  = 0.4886025119029199f*z;
  Y[3]  = 0.4886025119029199f*x;
  Y[4]  = 1.0925484305920792f*x*y;
  Y[5]  = 1.0925484305920792f*y*z;
  Y[6]  = 0.31539156525252005f*(3.f*z2 - 1.f);
  Y[7]  = 1.0925484305920792f*x*z;
  Y[8]  = 0.5462742152960396f*(x2 - y2);
  Y[9]  = 0.5900435899266435f*y*(3.f*x2 - y2);
  Y[10] = 2.890611442640554f*x*y*z;
  Y[11] = 0.4570457994644658f*y*(5.f*z2 - 1.f);
  Y[12] = 0.3731763325901154f*z*(5.f*z2 - 3.f);
  Y[13] = 0.4570457994644658f*x*(5.f*z2 - 1.f);
  Y[14] = 1.445305721320277f*z*(x2 - y2);
  Y[15] = 0.5900435899266435f*x*(x2 - 3.f*y2);
  float u = r*0.2f;
  int act = (u < 1.f);
  d_act[e] = act;
  float* R = d_Rb + e*8;
  if (act){
    float u2 = u*u; float u4 = u2*u2;
    float cut = 1.f + u4*u*(-21.f + u*(35.f - 15.f*u));
    float pref = 0.6324555320336759f * inv;
    #pragma unroll
    for (int b = 1; b <= 8; b++) R[b-1] = pref * sinpif((float)b*u) * cut;
  } else {
    #pragma unroll
    for (int b = 0; b < 8; b++) R[b] = 0.f;
  }
}

// ---------------- h0 = one_hot @ W_embed ----------------
__global__ void k_h0(const float* __restrict__ Wemb){
  int i = blockIdx.x*blockDim.x + threadIdx.x;
  int n = i >> 6, c = i & 63;
  d_h0[i] = Wemb[d_elem[n]*64 + c];
}

// ---------------- per-edge radial weights (both layers in one pass) ----------------
__global__ void k_edge_w(const float* __restrict__ Wrad){
  int idx = blockIdx.x*blockDim.x + threadIdx.x;
  if (idx >= EE*64) return;
  int e = idx >> 6, c = idx & 63;
  if (!d_act[e]) return;
  const float* R = d_Rb + e*8;
  float a0 = 0.f, a1 = 0.f;
  #pragma unroll
  for (int b = 0; b < 8; b++){
    float rb = R[b];
    a0 += rb*Wrad[b*64 + c];
    a1 += rb*Wrad[512 + b*64 + c];
  }
  d_w[0][e*64 + c] = a0;
  d_w[1][e*64 + c] = a1;
}

// ---------------- CSR gather: A[n,16,64] and B[n,256] ----------------
__global__ void k_gather(int layer, const int* __restrict__ ei){
  int n = blockIdx.x*4 + (threadIdx.x >> 5);
  int lane = threadIdx.x & 31;
  const float* __restrict__ h_in = (layer == 0) ? d_h0 : d_h1;
  float a0[16], a1[16];
  #pragma unroll
  for (int i = 0; i < 16; i++){ a0[i] = 0.f; a1[i] = 0.f; }
  int beg = d_rowptr[n], end = d_rowptr[n+1];
  for (int j = beg; j < end; j++){
    int e = d_perm[j];
    if (!d_act[e]) continue;
    int s = ei[e];
    float wh0 = d_w[layer][e*64 + lane]      * h_in[s*64 + lane];
    float wh1 = d_w[layer][e*64 + 32 + lane] * h_in[s*64 + 32 + lane];
    const float4* Yp = (const float4*)(d_Y + e*16);
    #pragma unroll
    for (int q = 0; q < 4; q++){
      float4 y = Yp[q];
      a0[4*q+0] += wh0*y.x; a1[4*q+0] += wh1*y.x;
      a0[4*q+1] += wh0*y.y; a1[4*q+1] += wh1*y.y;
      a0[4*q+2] += wh0*y.z; a1[4*q+2] += wh1*y.z;
      a0[4*q+3] += wh0*y.w; a1[4*q+3] += wh1*y.w;
    }
  }
  float* A = d_A[layer] + n*1024;
  #pragma unroll
  for (int lm = 0; lm < 16; lm++){ A[lm*64 + lane] = a0[lm]; A[lm*64 + 32 + lane] = a1[lm]; }
  float b0[4] = {0,0,0,0}, b1[4] = {0,0,0,0};
  #pragma unroll
  for (int lm = 0; lm < 16; lm++){
    int l = (lm == 0) ? 0 : (lm < 4) ? 1 : (lm < 9) ? 2 : 3;
    b0[l] += a0[lm]*a0[lm]; b1[l] += a1[lm]*a1[lm];
  }
  #pragma unroll
  for (int l = 0; l < 4; l++){
    d_Bf[n*256 + l*64 + lane]      = b0[l];
    d_Bf[n*256 + l*64 + 32 + lane] = b1[l];
  }
}

// ---------------- element-grouped GEMM: h_out = B @ Wp[layer][el] ----------------
// dynamic smem: Ws[16384] floats (64KB) + Bs[32*257] + nids[32]
#define GH_SMEM (16384*4 + 32*257*4 + 32*4)
__global__ void k_gemm_h(int layer, const float* __restrict__ Wprod){
  extern __shared__ float smem[];
  float* Ws = smem;                       // 16384
  float* Bs = smem + 16384;               // 32*257
  int*   nids = (int*)(smem + 16384 + 32*257);
  int el = blockIdx.x, t = blockIdx.y;
  int beg = d_elptr[el], cnt = d_elptr[el+1] - beg;
  int nb = t*32;
  if (nb >= cnt) return;
  int tid = threadIdx.x;
  const float4* W4 = (const float4*)(Wprod + (layer*NELEM + el)*16384);
  float4* Ws4 = (float4*)Ws;
  #pragma unroll
  for (int i = 0; i < 16; i++) Ws4[tid + i*256] = W4[tid + i*256];
  if (tid < 32){
    int k = nb + tid;
    nids[tid] = (k < cnt) ? d_nbyel[beg + k] : -1;
  }
  __syncthreads();
  for (int i = tid; i < 32*256; i += 256){
    int k = i >> 8, f = i & 255;
    int nn = nids[k];
    Bs[k*257 + f] = (nn >= 0) ? d_Bf[nn*256 + f] : 0.f;
  }
  __syncthreads();
  int nloc = tid >> 3, sub = tid & 7;
  float acc[8] = {0,0,0,0,0,0,0,0};
  const float* Brow = Bs + nloc*257;
  #pragma unroll 4
  for (int f = 0; f < 256; f++){
    float b = Brow[f];
    float4 w0 = Ws4[f*16 + sub*2];
    float4 w1 = Ws4[f*16 + sub*2 + 1];
    acc[0] += b*w0.x; acc[1] += b*w0.y; acc[2] += b*w0.z; acc[3] += b*w0.w;
    acc[4] += b*w1.x; acc[5] += b*w1.y; acc[6] += b*w1.z; acc[7] += b*w1.w;
  }
  int nn = nids[nloc];
  if (nn >= 0){
    float* ho = ((layer == 0) ? d_h1 : d_h2) + nn*64 + sub*8;
    #pragma unroll
    for (int j = 0; j < 8; j++) ho[j] = acc[j];
  }
}

// ---------------- backward: dB1 per element = Wp[1][el] @ w_read ----------------
__global__ void k_dB1e(const float* __restrict__ Wprod, const float* __restrict__ w_read){
  __shared__ float wr[64];
  int el = blockIdx.x, f = threadIdx.x;
  if (f < 64) wr[f] = w_read[f];
  __syncthreads();
  const float* W = Wprod + (NELEM + el)*16384 + f*64;
  float acc = 0.f;
  #pragma unroll
  for (int c = 0; c < 64; c++) acc += wr[c]*W[c];
  d_dB1e[el*256 + f] = acc;
}

// ---------------- element-grouped: dB0[n,f] = sum_c Wp[0][el][f,c] * dh1[n,c] ----------------
__global__ void k_gemm_dB0(const float* __restrict__ Wprod){
  __shared__ float dhs[32*65];
  __shared__ int nids[32];
  int el = blockIdx.x, t = blockIdx.y;
  int beg = d_elptr[el], cnt = d_elptr[el+1] - beg;
  int nb = t*32;
  if (nb >= cnt) return;
  int tid = threadIdx.x;
  if (tid < 32){
    int k = nb + tid;
    nids[tid] = (k < cnt) ? d_nbyel[beg + k] : -1;
  }
  __syncthreads();
  for (int i = tid; i < 32*64; i += 256){
    int k = i >> 6, c = i & 63;
    int nn = nids[k];
    dhs[k*65 + c] = (nn >= 0) ? d_dh1[nn*64 + c] : 0.f;
  }
  float Wr[64];
  {
    const float4* W4 = (const float4*)(Wprod + el*16384 + tid*64);
    float4* Wr4 = (float4*)Wr;
    #pragma unroll
    for (int i = 0; i < 16; i++) Wr4[i] = W4[i];
  }
  __syncthreads();
  #pragma unroll 4
  for (int k = 0; k < 32; k++){
    int nn = nids[k];
    if (nn < 0) break;
    const float* dh = dhs + k*65;
    float acc = 0.f;
    #pragma unroll
    for (int c = 0; c < 64; c++) acc += Wr[c]*dh[c];
    d_dB0[nn*256 + tid] = acc;
  }
}

// ---------------- node-centric layer backward ----------------
#define BFLY(p) { _Pragma("unroll") for (int off = 16; off > 0; off >>= 1) p += __shfl_xor_sync(0xffffffffu, p, off); }

template<int LAYER>
__global__ void k_nbwd(const float* __restrict__ Wrad, const int* __restrict__ ei){
  int n = blockIdx.x*4 + (threadIdx.x >> 5);
  int lane = threadIdx.x & 31;
  int beg = d_rowptr[n], end = d_rowptr[n+1];
  if (beg == end) return;
  const float* dB = (LAYER == 1) ? (d_dB1e + d_elem[n]*256) : (d_dB0 + n*256);
  float db0[4], db1[4];
  #pragma unroll
  for (int l = 0; l < 4; l++){ db0[l] = dB[l*64 + lane]; db1[l] = dB[l*64 + 32 + lane]; }
  const float* A = d_A[LAYER] + n*1024;
  float dA0[16], dA1[16];
  #pragma unroll
  for (int lm = 0; lm < 16; lm++){
    int l = (lm == 0) ? 0 : (lm < 4) ? 1 : (lm < 9) ? 2 : 3;
    dA0[lm] = 2.f*A[lm*64 + lane]      * db0[l];
    dA1[lm] = 2.f*A[lm*64 + 32 + lane] * db1[l];
  }
  float wr0[8], wr1[8];
  #pragma unroll
  for (int b = 0; b < 8; b++){ wr0[b] = Wrad[b*64 + lane]; wr1[b] = Wrad[b*64 + 32 + lane]; }
  const float* __restrict__ h_in = (LAYER == 0) ? d_h0 : d_h1;
  for (int j = beg; j < end; j++){
    int e = d_perm[j];
    if (!d_act[e]) continue;
    int s = ei[e];
    float w0 = d_w[LAYER][e*64 + lane], w1 = d_w[LAYER][e*64 + 32 + lane];
    float hv0 = h_in[s*64 + lane],      hv1 = h_in[s*64 + 32 + lane];
    float wh0 = w0*hv0, wh1 = w1*hv1;
    float g0 = 0.f, g1 = 0.f;
    float dy[16];
    #pragma unroll
    for (int lm = 0; lm < 16; lm++){
      float y = d_Y[e*16 + lm];
      g0 += dA0[lm]*y; g1 += dA1[lm]*y;
      float p = dA0[lm]*wh0 + dA1[lm]*wh1;
      BFLY(p);
      dy[lm] = p;
    }
    float t0 = g0*hv0, t1 = g1*hv1;
    float dr[8];
    #pragma unroll
    for (int b = 0; b < 8; b++){
      float p = t0*wr0[b] + t1*wr1[b];
      BFLY(p);
      dr[b] = p;
    }
    if (lane == 0){
      float4* dyp = (float4*)(d_dY + e*16);
      float4* drp = (float4*)(d_dR + e*8);
      if (LAYER == 1){
        dyp[0] = make_float4(dy[0],dy[1],dy[2],dy[3]);
        dyp[1] = make_float4(dy[4],dy[5],dy[6],dy[7]);
        dyp[2] = make_float4(dy[8],dy[9],dy[10],dy[11]);
        dyp[3] = make_float4(dy[12],dy[13],dy[14],dy[15]);
        drp[0] = make_float4(dr[0],dr[1],dr[2],dr[3]);
        drp[1] = make_float4(dr[4],dr[5],dr[6],dr[7]);
      } else {
        #pragma unroll
        for (int q = 0; q < 4; q++){
          float4 v = dyp[q];
          v.x += dy[4*q]; v.y += dy[4*q+1]; v.z += dy[4*q+2]; v.w += dy[4*q+3];
          dyp[q] = v;
        }
        #pragma unroll
        for (int q = 0; q < 2; q++){
          float4 v = drp[q];
          v.x += dr[4*q]; v.y += dr[4*q+1]; v.z += dr[4*q+2]; v.w += dr[4*q+3];
          drp[q] = v;
        }
      }
    }
    if (LAYER == 1){
      atomicAdd(&d_dh1[s*64 + lane],      g0*w0);
      atomicAdd(&d_dh1[s*64 + 32 + lane], g1*w1);
    }
  }
}

// ---------------- backward through geometry ----------------
__global__ void k_geom_bwd(const int* __restrict__ ei){
  int e = blockIdx.x*blockDim.x + threadIdx.x;
  if (e >= EE) return;
  if (!d_act[e]) return;
  float vx = d_vec[3*e], vy = d_vec[3*e+1], vz = d_vec[3*e+2];
  float r = d_r[e], inv = 1.f/r;
  float x = vx*inv, y = vy*inv, z = vz*inv;
  float x2 = x*x, y2 = y*y, z2 = z*z;
  const float* dY = d_dY + e*16;
  float gx = 0.f, gy = 0.f, gz = 0.f;
  gy += 0.4886025119029199f*dY[1];
  gz += 0.4886025119029199f*dY[2];
  gx += 0.4886025119029199f*dY[3];
  gx += 1.0925484305920792f*y*dY[4];  gy += 1.0925484305920792f*x*dY[4];
  gy += 1.0925484305920792f*z*dY[5];  gz += 1.0925484305920792f*y*dY[5];
  gz += 1.8923493915151203f*z*dY[6];
  gx += 1.0925484305920792f*z*dY[7];  gz += 1.0925484305920792f*x*dY[7];
  gx += 1.0925484305920792f*x*dY[8];  gy -= 1.0925484305920792f*y*dY[8];
  gx += 3.540261539559861f*x*y*dY[9]; gy += 1.7701307697799304f*(x2-y2)*dY[9];
  gx += 2.890611442640554f*y*z*dY[10]; gy += 2.890611442640554f*x*z*dY[10]; gz += 2.890611442640554f*x*y*dY[10];
  gy += 0.4570457994644658f*(5.f*z2-1.f)*dY[11]; gz += 4.570457994644658f*y*z*dY[11];
  gz += 0.3731763325901154f*(15.f*z2-3.f)*dY[12];
  gx += 0.4570457994644658f*(5.f*z2-1.f)*dY[13]; gz += 4.570457994644658f*x*z*dY[13];
  gx += 2.890611442640554f*x*z*dY[14]; gy -= 2.890611442640554f*y*z*dY[14]; gz += 1.445305721320277f*(x2-y2)*dY[14];
  gx += 1.7701307697799304f*(x2-y2)*dY[15]; gy -= 3.540261539559861f*x*y*dY[15];
  float u = r*0.2f;
  float u2 = u*u; float u4 = u2*u2;
  float omu = 1.f - u;
  float cut  = 1.f + u4*u*(-21.f + u*(35.f - 15.f*u));
  float cutp = -105.f*u4*omu*omu;
  const float* dR = d_dR + e*8;
  const float pref = 0.6324555320336759f;
  const float PI_F = 3.14159265358979323846f;
  float drdr = 0.f;
  #pragma unroll
  for (int b = 1; b <= 8; b++){
    float sp, cp;
    sincospif((float)b*u, &sp, &cp);
    float dterm = pref*(((float)b*PI_F*0.2f)*cp*inv - sp*inv*inv)*cut
                + pref*sp*inv*cutp*0.2f;
    drdr += dR[b-1]*dterm;
  }
  float gdv = gx*vx + gy*vy + gz*vz;
  float inv3 = inv*inv*inv;
  float dvx = gx*inv - gdv*vx*inv3 + drdr*vx*inv;
  float dvy = gy*inv - gdv*vy*inv3 + drdr*vy*inv;
  float dvz = gz*inv - gdv*vz*inv3 + drdr*vz*inv;
  int s = ei[e], n = ei[EE+e];
  atomicAdd(&d_gpos[3*n],   dvx); atomicAdd(&d_gpos[3*n+1],  dvy); atomicAdd(&d_gpos[3*n+2],  dvz);
  atomicAdd(&d_gpos[3*s],  -dvx); atomicAdd(&d_gpos[3*s+1], -dvy); atomicAdd(&d_gpos[3*s+2], -dvz);
}

// ---------------- energies ----------------
__global__ void k_energy(const float* __restrict__ w_read, const float* __restrict__ ae,
                         const int* __restrict__ batch){
  __shared__ float part[GG];
  int t = threadIdx.x;
  if (t < GG) part[t] = 0.f;
  __syncthreads();
  int n = blockIdx.x*256 + t;
  const float* h = d_h2 + n*64;
  float acc = 0.f;
  #pragma unroll
  for (int c = 0; c < 64; c++) acc += h[c]*w_read[c];
  acc += ae[d_elem[n]];
  atomicAdd(&part[batch[n]], acc);
  __syncthreads();
  if (t < GG) atomicAdd(&d_eng[t], part[t]);
}

__global__ void k_final(float* __restrict__ out){
  int i = blockIdx.x*blockDim.x + threadIdx.x;
  if (i < GG) out[i] = d_eng[i];
  if (i < NN*3) out[GG + i] = -d_gpos[i];
}

// ---------------- launch ----------------
extern "C" void kernel_launch(void* const* d_in, const int* in_sizes, int n_in,
                              void* d_out, int out_size){
  const float* pos    = (const float*)d_in[0];
  const float* attrs  = (const float*)d_in[1];
  const float* shifts = (const float*)d_in[2];
  const float* Wemb   = (const float*)d_in[3];
  const float* aew    = (const float*)d_in[4];
  const float* Wrad   = (const float*)d_in[5];
  const float* Wprod  = (const float*)d_in[6];
  const float* wread  = (const float*)d_in[7];
  const int*   ei     = (const int*)d_in[8];
  const int*   batch  = (const int*)d_in[9];
  float* out = (float*)d_out;

  static bool attr_done = false;
  if (!attr_done){
    cudaFuncSetAttribute(k_gemm_h, cudaFuncAttributeMaxDynamicSharedMemorySize, GH_SMEM);
    attr_done = true;
  }

  k_prep<<<NN*64/256, 256>>>(attrs);
  k_hist<<<EE/256, 256>>>(ei);
  k_scan<<<1, 256>>>();
  k_fill<<<EE/256, 256>>>(ei);
  k_geom<<<EE/256, 256>>>(pos, shifts, ei);
  k_h0<<<NN*64/256, 256>>>(Wemb);
  k_edge_w<<<EE*64/256, 256>>>(Wrad);

  // layer 0 forward
  k_gather<<<NN/4, 128>>>(0, ei);
  k_gemm_h<<<dim3(NELEM, TILES), 256, GH_SMEM>>>(0, Wprod);
  // layer 1 forward
  k_gather<<<NN/4, 128>>>(1, ei);
  k_gemm_h<<<dim3(NELEM, TILES), 256, GH_SMEM>>>(1, Wprod);

  k_energy<<<NN/256, 256>>>(wread, aew, batch);

  // backward
  k_dB1e<<<NELEM, 256>>>(Wprod, wread);
  k_nbwd<1><<<NN/4, 128>>>(Wrad + 512, ei);
  k_gemm_dB0<<<dim3(NELEM, TILES), 256>>>(Wprod);
  k_nbwd<0><<<NN/4, 128>>>(Wrad, ei);
  k_geom_bwd<<<EE/256, 256>>>(ei);

  k_final<<<(NN*3 + 255)/256, 256>>>(out);
}

// round 4
// speedup vs baseline: 2.7211x; 1.1449x over previous
#include <cuda_runtime.h>

#define NN 8192
#define EE 65536
#define GG 16
#define NELEM 10
#define TILES 256

// ---------------- persistent device scratch ----------------
__device__ float d_vec[EE*3];     // unit vectors (active only)
__device__ float d_r[EE];         // 1/r (active only)
__device__ int   d_act[EE];
__device__ float d_Y[EE*16];
__device__ float d_Rb[EE*8];
__device__ float d_dRb[EE*8];     // dR/dr
__device__ float d_A[NN*1024];    // layer0 A only
__device__ float d_Bf[NN*256];
__device__ float d_h1[NN*64];
__device__ float d_h2[NN*64];
__device__ float d_dh1[NN*64];
__device__ float d_dB0[NN*256];
__device__ float d_dB1e[NELEM*256];
__device__ float d_gpos[NN*3];
__device__ float d_eng[GG];
__device__ int d_elem[NN];
__device__ int d_deg[NN];
__device__ int d_rowptr[NN+1];
__device__ int d_cursor[NN];
__device__ int d_perm[EE];
__device__ int d_elptr[NELEM+1];
__device__ int d_elcur[NELEM];
__device__ int d_nbyel[NN];

#define BFLY(p) { _Pragma("unroll") for (int off = 16; off > 0; off >>= 1) p += __shfl_xor_sync(0xffffffffu, p, off); }

__device__ __forceinline__ float dot8(float4 a, float4 b, const float w[8]){
  return a.x*w[0]+a.y*w[1]+a.z*w[2]+a.w*w[3]+b.x*w[4]+b.y*w[5]+b.z*w[6]+b.w*w[7];
}

// ---------------- setup ----------------
__global__ void k_prep(const float* __restrict__ attrs){
  int i = blockIdx.x*blockDim.x + threadIdx.x;   // NN*64
  d_dh1[i] = 0.f;
  if (i < GG) d_eng[i] = 0.f;
  if (i < NN){
    int el = 0;
    const float* a = attrs + i*NELEM;
    #pragma unroll
    for (int e = 1; e < NELEM; e++) if (a[e] > 0.5f) el = e;
    d_elem[i] = el;
    d_deg[i]  = 0;
    d_gpos[3*i] = 0.f; d_gpos[3*i+1] = 0.f; d_gpos[3*i+2] = 0.f;
  }
}

// ---------------- geometry + active-degree histogram ----------------
__global__ void k_geom(const float* __restrict__ pos, const float* __restrict__ shifts,
                       const int* __restrict__ ei){
  int e = blockIdx.x*blockDim.x + threadIdx.x;
  if (e >= EE) return;
  int s = ei[e], n = ei[EE+e];
  float vx = pos[3*n]   - pos[3*s]   + shifts[3*e];
  float vy = pos[3*n+1] - pos[3*s+1] + shifts[3*e+1];
  float vz = pos[3*n+2] - pos[3*s+2] + shifts[3*e+2];
  float r = sqrtf(vx*vx + vy*vy + vz*vz + 1e-9f);
  float u = r*0.2f;
  int act = (u < 1.f);
  d_act[e] = act;
  if (!act) return;
  atomicAdd(&d_deg[n], 1);
  float inv = 1.f/r;
  float x = vx*inv, y = vy*inv, z = vz*inv;
  d_vec[3*e] = x; d_vec[3*e+1] = y; d_vec[3*e+2] = z;
  d_r[e] = inv;
  float x2 = x*x, y2 = y*y, z2 = z*z;
  float* Y = d_Y + e*16;
  Y[0]  = 0.28209479177387814f;
  Y[1]  = 0.4886025119029199f*y;
  Y[2]  = 0.4886025119029199f*z;
  Y[3]  = 0.4886025119029199f*x;
  Y[4]  = 1.0925484305920792f*x*y;
  Y[5]  = 1.0925484305920792f*y*z;
  Y[6]  = 0.31539156525252005f*(3.f*z2 - 1.f);
  Y[7]  = 1.0925484305920792f*x*z;
  Y[8]  = 0.5462742152960396f*(x2 - y2);
  Y[9]  = 0.5900435899266435f*y*(3.f*x2 - y2);
  Y[10] = 2.890611442640554f*x*y*z;
  Y[11] = 0.4570457994644658f*y*(5.f*z2 - 1.f);
  Y[12] = 0.3731763325901154f*z*(5.f*z2 - 3.f);
  Y[13] = 0.4570457994644658f*x*(5.f*z2 - 1.f);
  Y[14] = 1.445305721320277f*z*(x2 - y2);
  Y[15] = 0.5900435899266435f*x*(x2 - 3.f*y2);
  float u2 = u*u; float u4 = u2*u2;
  float omu = 1.f - u;
  float cut  = 1.f + u4*u*(-21.f + u*(35.f - 15.f*u));
  float cutp = -105.f*u4*omu*omu;
  const float pref = 0.6324555320336759f;
  const float PI_F = 3.14159265358979323846f;
  float* R = d_Rb + e*8;
  float* D = d_dRb + e*8;
  #pragma unroll
  for (int b = 1; b <= 8; b++){
    float sp, cp;
    sincospif((float)b*u, &sp, &cp);
    R[b-1] = pref*sp*inv*cut;
    D[b-1] = pref*(((float)b*PI_F*0.2f)*cp*inv - sp*inv*inv)*cut
           + pref*sp*inv*cutp*0.2f;
  }
}

// ---------------- one-block scan: rowptr + element offsets ----------------
__global__ void k_scan(){
  __shared__ int wsum[8];
  __shared__ int elbin[NELEM];
  int t = threadIdx.x;          // 256 threads, 32 nodes each
  int lane = t & 31, w = t >> 5;
  if (t < NELEM) elbin[t] = 0;
  __syncthreads();
  int base = t*32;
  int dg[32];
  const int4* dp = (const int4*)(d_deg + base);
  #pragma unroll
  for (int q = 0; q < 8; q++){
    int4 v = dp[q];
    dg[4*q] = v.x; dg[4*q+1] = v.y; dg[4*q+2] = v.z; dg[4*q+3] = v.w;
  }
  int loc[32]; int s = 0;
  #pragma unroll
  for (int i = 0; i < 32; i++){ loc[i] = s; s += dg[i]; }
  for (int i = 0; i < 32; i++) atomicAdd(&elbin[d_elem[base+i]], 1);
  int pref = s;
  #pragma unroll
  for (int off = 1; off < 32; off <<= 1){
    int v = __shfl_up_sync(0xffffffffu, pref, off);
    if (lane >= off) pref += v;
  }
  if (lane == 31) wsum[w] = pref;
  __syncthreads();
  if (t == 0){
    int a = 0;
    #pragma unroll
    for (int k = 0; k < 8; k++){ int tmp = wsum[k]; wsum[k] = a; a += tmp; }
    d_rowptr[NN] = a;
    int b = 0;
    #pragma unroll
    for (int e = 0; e < NELEM; e++){ d_elptr[e] = b; d_elcur[e] = b; b += elbin[e]; }
    d_elptr[NELEM] = b;
  }
  __syncthreads();
  int excl = pref - s + wsum[w];
  #pragma unroll
  for (int i = 0; i < 32; i++){
    int v = excl + loc[i];
    d_rowptr[base+i] = v; d_cursor[base+i] = v;
  }
}

// ---------------- fill CSR (active only) + node-by-element + dB1e ----------------
__global__ void k_fill_misc(const int* __restrict__ ei, const float* __restrict__ Wprod,
                            const float* __restrict__ w_read){
  if (blockIdx.x < 256){
    int idx = blockIdx.x*256 + threadIdx.x;
    if (idx < EE && d_act[idx]){
      int p = atomicAdd(&d_cursor[ei[EE+idx]], 1);
      d_perm[p] = idx;
    }
    if (idx < NN){
      int q = atomicAdd(&d_elcur[d_elem[idx]], 1);
      d_nbyel[q] = idx;
    }
  } else {
    __shared__ float wr[64];
    int el = blockIdx.x - 256, f = threadIdx.x;
    if (f < 64) wr[f] = w_read[f];
    __syncthreads();
    const float* W = Wprod + (NELEM + el)*16384 + f*64;
    float acc = 0.f;
    #pragma unroll
    for (int c = 0; c < 64; c++) acc += wr[c]*W[c];
    d_dB1e[el*256 + f] = acc;
  }
}

// ---------------- gather layer 0: A (stored) + B ----------------
__global__ void k_gather0(const int* __restrict__ ei, const float* __restrict__ Wemb,
                          const float* __restrict__ Wrad){
  int n = blockIdx.x*4 + (threadIdx.x >> 5);
  int lane = threadIdx.x & 31;
  float wr0[8], wr1[8];
  #pragma unroll
  for (int b = 0; b < 8; b++){ wr0[b] = Wrad[b*64+lane]; wr1[b] = Wrad[b*64+32+lane]; }
  float a0[16], a1[16];
  #pragma unroll
  for (int i = 0; i < 16; i++){ a0[i] = 0.f; a1[i] = 0.f; }
  int beg = d_rowptr[n], end = d_rowptr[n+1];
  for (int base = beg; base < end; base += 32){
    int j = base + lane;
    int e = 0, els = 0;
    if (j < end){ e = d_perm[j]; els = d_elem[ei[e]]; }
    int m = min(32, end - base);
    for (int k = 0; k < m; k++){
      int ek  = __shfl_sync(0xffffffffu, e, k);
      int elk = __shfl_sync(0xffffffffu, els, k);
      float4 R0 = *(const float4*)(d_Rb + ek*8);
      float4 R1 = *(const float4*)(d_Rb + ek*8 + 4);
      float w0 = dot8(R0, R1, wr0);
      float w1 = dot8(R0, R1, wr1);
      float wh0 = w0 * Wemb[elk*64 + lane];
      float wh1 = w1 * Wemb[elk*64 + 32 + lane];
      const float4* Yp = (const float4*)(d_Y + ek*16);
      #pragma unroll
      for (int q = 0; q < 4; q++){
        float4 y = Yp[q];
        a0[4*q+0] += wh0*y.x; a1[4*q+0] += wh1*y.x;
        a0[4*q+1] += wh0*y.y; a1[4*q+1] += wh1*y.y;
        a0[4*q+2] += wh0*y.z; a1[4*q+2] += wh1*y.z;
        a0[4*q+3] += wh0*y.w; a1[4*q+3] += wh1*y.w;
      }
    }
  }
  float* A = d_A + n*1024;
  #pragma unroll
  for (int lm = 0; lm < 16; lm++){ A[lm*64 + lane] = a0[lm]; A[lm*64 + 32 + lane] = a1[lm]; }
  float b0[4] = {0,0,0,0}, b1[4] = {0,0,0,0};
  #pragma unroll
  for (int lm = 0; lm < 16; lm++){
    int l = (lm == 0) ? 0 : (lm < 4) ? 1 : (lm < 9) ? 2 : 3;
    b0[l] += a0[lm]*a0[lm]; b1[l] += a1[lm]*a1[lm];
  }
  #pragma unroll
  for (int l = 0; l < 4; l++){
    d_Bf[n*256 + l*64 + lane]      = b0[l];
    d_Bf[n*256 + l*64 + 32 + lane] = b1[l];
  }
}

// ---------------- per-edge backward core (Jacobian fused, grads -> gpos) ----------------
template<int LAYER>
__device__ __forceinline__ void edge_bwd_loop(
    int n, int lane, int beg, int end,
    const int* __restrict__ ei, const float* __restrict__ Wemb,
    const float dA0[16], const float dA1[16],
    const float wr0[8], const float wr1[8])
{
  float accx = 0.f, accy = 0.f, accz = 0.f;   // lane0: receiver-node gpos accum
  const float c1 = 0.4886025119029199f;
  for (int base = beg; base < end; base += 32){
    int j = base + lane;
    int e = 0, s = 0, els = 0;
    if (j < end){ e = d_perm[j]; s = ei[e]; if (LAYER == 0) els = d_elem[s]; }
    int m = min(32, end - base);
    for (int k = 0; k < m; k++){
      int ek = __shfl_sync(0xffffffffu, e, k);
      int sk = __shfl_sync(0xffffffffu, s, k);
      float4 R0 = *(const float4*)(d_Rb + ek*8);
      float4 R1 = *(const float4*)(d_Rb + ek*8 + 4);
      float4 D0 = *(const float4*)(d_dRb + ek*8);
      float4 D1 = *(const float4*)(d_dRb + ek*8 + 4);
      float w0 = dot8(R0, R1, wr0);
      float w1 = dot8(R0, R1, wr1);
      float hv0, hv1;
      if (LAYER == 1){
        hv0 = d_h1[sk*64 + lane]; hv1 = d_h1[sk*64 + 32 + lane];
      } else {
        int elk = __shfl_sync(0xffffffffu, els, k);
        hv0 = Wemb[elk*64 + lane]; hv1 = Wemb[elk*64 + 32 + lane];
      }
      float wh0 = w0*hv0, wh1 = w1*hv1;
      const float4* Yp = (const float4*)(d_Y + ek*16);
      float Yv[16];
      #pragma unroll
      for (int q = 0; q < 4; q++){
        float4 y = Yp[q];
        Yv[4*q] = y.x; Yv[4*q+1] = y.y; Yv[4*q+2] = y.z; Yv[4*q+3] = y.w;
      }
      float g0 = 0.f, g1 = 0.f;
      #pragma unroll
      for (int lm = 0; lm < 16; lm++){ g0 += dA0[lm]*Yv[lm]; g1 += dA1[lm]*Yv[lm]; }
      float s0 = dot8(D0, D1, wr0);
      float s1 = dot8(D0, D1, wr1);
      // unit vector + inv (uniform loads)
      float x = d_vec[3*ek], y = d_vec[3*ek+1], z = d_vec[3*ek+2];
      float inv = d_r[ek];
      float x2my2 = x*x - y*y;
      float z2 = z*z;
      float c4x = 1.0925484305920792f*x, c4y = 1.0925484305920792f*y, c4z = 1.0925484305920792f*z;
      float txy = 2.890611442640554f*x*y, txz = 2.890611442640554f*x*z, tyz = 2.890611442640554f*y*z;
      float q13 = 0.4570457994644658f*(5.f*z2 - 1.f);
      float e9  = 3.540261539559861f*x*y;
      float e15 = 1.7701307697799304f*x2my2;
      float pz6 = 1.8923493915151203f*z;
      float q11y = 4.570457994644658f*y*z, q11x = 4.570457994644658f*x*z;
      float p12 = 0.3731763325901154f*(15.f*z2 - 3.f);
      float p14 = 1.445305721320277f*x2my2;
      float px0 = c1*dA0[3] + c4y*dA0[4] + c4z*dA0[7] + c4x*dA0[8] + e9*dA0[9]
                + tyz*dA0[10] + q13*dA0[13] + txz*dA0[14] + e15*dA0[15];
      float py0 = c1*dA0[1] + c4x*dA0[4] + c4z*dA0[5] - c4y*dA0[8] + e15*dA0[9]
                + txz*dA0[10] + q13*dA0[11] - tyz*dA0[14] - e9*dA0[15];
      float pz0 = c1*dA0[2] + c4y*dA0[5] + pz6*dA0[6] + c4x*dA0[7] + txy*dA0[10]
                + q11y*dA0[11] + p12*dA0[12] + q11x*dA0[13] + p14*dA0[14];
      float px1 = c1*dA1[3] + c4y*dA1[4] + c4z*dA1[7] + c4x*dA1[8] + e9*dA1[9]
                + tyz*dA1[10] + q13*dA1[13] + txz*dA1[14] + e15*dA1[15];
      float py1 = c1*dA1[1] + c4x*dA1[4] + c4z*dA1[5] - c4y*dA1[8] + e15*dA1[9]
                + txz*dA1[10] + q13*dA1[11] - tyz*dA1[14] - e9*dA1[15];
      float pz1 = c1*dA1[2] + c4y*dA1[5] + pz6*dA1[6] + c4x*dA1[7] + txy*dA1[10]
                + q11y*dA1[11] + p12*dA1[12] + q11x*dA1[13] + p14*dA1[14];
      float pgx = wh0*px0 + wh1*px1;
      float pgy = wh0*py0 + wh1*py1;
      float pgz = wh0*pz0 + wh1*pz1;
      float prad = g0*hv0*s0 + g1*hv1*s1;
      BFLY(pgx); BFLY(pgy); BFLY(pgz); BFLY(prad);
      if (lane == 0){
        float gdotu = pgx*x + pgy*y + pgz*z;
        float dvx = inv*(pgx - gdotu*x) + prad*x;
        float dvy = inv*(pgy - gdotu*y) + prad*y;
        float dvz = inv*(pgz - gdotu*z) + prad*z;
        accx += dvx; accy += dvy; accz += dvz;
        atomicAdd(&d_gpos[3*sk],   -dvx);
        atomicAdd(&d_gpos[3*sk+1], -dvy);
        atomicAdd(&d_gpos[3*sk+2], -dvz);
      }
      if (LAYER == 1){
        atomicAdd(&d_dh1[sk*64 + lane],      g0*w0);
        atomicAdd(&d_dh1[sk*64 + 32 + lane], g1*w1);
      }
    }
  }
  if (lane == 0 && beg < end){
    atomicAdd(&d_gpos[3*n],   accx);
    atomicAdd(&d_gpos[3*n+1], accy);
    atomicAdd(&d_gpos[3*n+2], accz);
  }
}

// ---------------- fused layer-1 gather (B) + layer-1 backward ----------------
__global__ void k_gfused1(const int* __restrict__ ei, const float* __restrict__ Wemb,
                          const float* __restrict__ Wrad){
  int n = blockIdx.x*4 + (threadIdx.x >> 5);
  int lane = threadIdx.x & 31;
  float wr0[8], wr1[8];
  #pragma unroll
  for (int b = 0; b < 8; b++){ wr0[b] = Wrad[b*64+lane]; wr1[b] = Wrad[b*64+32+lane]; }
  float a0[16], a1[16];
  #pragma unroll
  for (int i = 0; i < 16; i++){ a0[i] = 0.f; a1[i] = 0.f; }
  int beg = d_rowptr[n], end = d_rowptr[n+1];
  for (int base = beg; base < end; base += 32){
    int j = base + lane;
    int e = 0, s = 0;
    if (j < end){ e = d_perm[j]; s = ei[e]; }
    int m = min(32, end - base);
    for (int k = 0; k < m; k++){
      int ek = __shfl_sync(0xffffffffu, e, k);
      int sk = __shfl_sync(0xffffffffu, s, k);
      float4 R0 = *(const float4*)(d_Rb + ek*8);
      float4 R1 = *(const float4*)(d_Rb + ek*8 + 4);
      float w0 = dot8(R0, R1, wr0);
      float w1 = dot8(R0, R1, wr1);
      float wh0 = w0 * d_h1[sk*64 + lane];
      float wh1 = w1 * d_h1[sk*64 + 32 + lane];
      const float4* Yp = (const float4*)(d_Y + ek*16);
      #pragma unroll
      for (int q = 0; q < 4; q++){
        float4 y = Yp[q];
        a0[4*q+0] += wh0*y.x; a1[4*q+0] += wh1*y.x;
        a0[4*q+1] += wh0*y.y; a1[4*q+1] += wh1*y.y;
        a0[4*q+2] += wh0*y.z; a1[4*q+2] += wh1*y.z;
        a0[4*q+3] += wh0*y.w; a1[4*q+3] += wh1*y.w;
      }
    }
  }
  // B1 for gemm_h1
  float b0[4] = {0,0,0,0}, b1[4] = {0,0,0,0};
  #pragma unroll
  for (int lm = 0; lm < 16; lm++){
    int l = (lm == 0) ? 0 : (lm < 4) ? 1 : (lm < 9) ? 2 : 3;
    b0[l] += a0[lm]*a0[lm]; b1[l] += a1[lm]*a1[lm];
  }
  #pragma unroll
  for (int l = 0; l < 4; l++){
    d_Bf[n*256 + l*64 + lane]      = b0[l];
    d_Bf[n*256 + l*64 + 32 + lane] = b1[l];
  }
  if (beg == end) return;
  // dA = 2*A*dB1e[elem]
  const float* dB = d_dB1e + d_elem[n]*256;
  #pragma unroll
  for (int lm = 0; lm < 16; lm++){
    int l = (lm == 0) ? 0 : (lm < 4) ? 1 : (lm < 9) ? 2 : 3;
    a0[lm] = 2.f*a0[lm]*dB[l*64 + lane];
    a1[lm] = 2.f*a1[lm]*dB[l*64 + 32 + lane];
  }
  edge_bwd_loop<1>(n, lane, beg, end, ei, Wemb, a0, a1, wr0, wr1);
}

// ---------------- layer-0 backward ----------------
__global__ void k_nbwd0(const int* __restrict__ ei, const float* __restrict__ Wemb,
                        const float* __restrict__ Wrad){
  int n = blockIdx.x*4 + (threadIdx.x >> 5);
  int lane = threadIdx.x & 31;
  int beg = d_rowptr[n], end = d_rowptr[n+1];
  if (beg == end) return;
  float wr0[8], wr1[8];
  #pragma unroll
  for (int b = 0; b < 8; b++){ wr0[b] = Wrad[b*64+lane]; wr1[b] = Wrad[b*64+32+lane]; }
  const float* dB = d_dB0 + n*256;
  const float* A  = d_A + n*1024;
  float dA0[16], dA1[16];
  #pragma unroll
  for (int lm = 0; lm < 16; lm++){
    int l = (lm == 0) ? 0 : (lm < 4) ? 1 : (lm < 9) ? 2 : 3;
    dA0[lm] = 2.f*A[lm*64 + lane]      * dB[l*64 + lane];
    dA1[lm] = 2.f*A[lm*64 + 32 + lane] * dB[l*64 + 32 + lane];
  }
  edge_bwd_loop<0>(n, lane, beg, end, ei, Wemb, dA0, dA1, wr0, wr1);
}

// ---------------- element-grouped GEMM: h_out = B @ Wp[layer][el] ----------------
#define GH_SMEM (16384*4 + 32*257*4 + 128)
__global__ void k_gemm_h(int layer, const float* __restrict__ Wprod){
  extern __shared__ float sm[];
  float* Ws = sm;
  float* Bs = sm + 16384;
  int* nids = (int*)(sm + 16384 + 32*257);
  int el = blockIdx.x, t = blockIdx.y;
  int beg = d_elptr[el], cnt = d_elptr[el+1] - beg;
  int nb = t*32;
  if (nb >= cnt) return;
  int tid = threadIdx.x;   // 128
  const float4* W4 = (const float4*)(Wprod + (layer*NELEM + el)*16384);
  float4* Ws4 = (float4*)Ws;
  #pragma unroll
  for (int i = 0; i < 32; i++) Ws4[tid + i*128] = W4[tid + i*128];
  if (tid < 32){
    int k = nb + tid;
    nids[tid] = (k < cnt) ? d_nbyel[beg + k] : -1;
  }
  __syncthreads();
  for (int i = tid; i < 32*256; i += 128){
    int k = i >> 8, f = i & 255;
    int nn = nids[k];
    Bs[k*257 + f] = (nn >= 0) ? d_Bf[nn*256 + f] : 0.f;
  }
  __syncthreads();
  int ng = tid >> 3, cg = tid & 7;
  const float* B0 = Bs + (2*ng)*257;
  const float* B1 = B0 + 257;
  float acc0[8] = {0,0,0,0,0,0,0,0};
  float acc1[8] = {0,0,0,0,0,0,0,0};
  #pragma unroll 4
  for (int f = 0; f < 256; f++){
    float bb0 = B0[f], bb1 = B1[f];
    float4 w0 = Ws4[f*16 + cg*2];
    float4 w1 = Ws4[f*16 + cg*2 + 1];
    acc0[0] += bb0*w0.x; acc0[1] += bb0*w0.y; acc0[2] += bb0*w0.z; acc0[3] += bb0*w0.w;
    acc0[4] += bb0*w1.x; acc0[5] += bb0*w1.y; acc0[6] += bb0*w1.z; acc0[7] += bb0*w1.w;
    acc1[0] += bb1*w0.x; acc1[1] += bb1*w0.y; acc1[2] += bb1*w0.z; acc1[3] += bb1*w0.w;
    acc1[4] += bb1*w1.x; acc1[5] += bb1*w1.y; acc1[6] += bb1*w1.z; acc1[7] += bb1*w1.w;
  }
  float* out = (layer == 0) ? d_h1 : d_h2;
  int n0 = nids[2*ng], n1 = nids[2*ng+1];
  if (n0 >= 0){
    float4* o = (float4*)(out + n0*64 + cg*8);
    o[0] = make_float4(acc0[0],acc0[1],acc0[2],acc0[3]);
    o[1] = make_float4(acc0[4],acc0[5],acc0[6],acc0[7]);
  }
  if (n1 >= 0){
    float4* o = (float4*)(out + n1*64 + cg*8);
    o[0] = make_float4(acc1[0],acc1[1],acc1[2],acc1[3]);
    o[1] = make_float4(acc1[4],acc1[5],acc1[6],acc1[7]);
  }
}

// ---------------- element-grouped: dB0[n,f] = sum_c Wp[0][el][f,c]*dh1[n,c] ----------------
#define DB0_SMEM (64*264*4 + 32*66*4 + 128)
__global__ void k_gemm_dB0(const float* __restrict__ Wprod){
  extern __shared__ float sm[];
  float* Wt = sm;                       // [c][f] : 64 x 264
  float* dhs = sm + 64*264;             // [node][c] : 32 x 66
  int* nids = (int*)(sm + 64*264 + 32*66);
  int el = blockIdx.x, t = blockIdx.y;
  int beg = d_elptr[el], cnt = d_elptr[el+1] - beg;
  int nb = t*32;
  if (nb >= cnt) return;
  int tid = threadIdx.x;   // 256
  const float* W = Wprod + el*16384;
  for (int i = tid; i < 16384; i += 256){
    int f = i >> 6, c = i & 63;
    Wt[c*264 + f] = W[i];
  }
  if (tid < 32){
    int k = nb + tid;
    nids[tid] = (k < cnt) ? d_nbyel[beg + k] : -1;
  }
  __syncthreads();
  for (int i = tid; i < 32*64; i += 256){
    int k = i >> 6, c = i & 63;
    int nn = nids[k];
    dhs[k*66 + c] = (nn >= 0) ? d_dh1[nn*64 + c] : 0.f;
  }
  __syncthreads();
  int ng = tid >> 4, fg = tid & 15;     // 16 node-pairs x 16 f-groups
  float acc0[16], acc1[16];
  #pragma unroll
  for (int i = 0; i < 16; i++){ acc0[i] = 0.f; acc1[i] = 0.f; }
  #pragma unroll 2
  for (int c = 0; c < 64; c++){
    float dd0 = dhs[(2*ng)*66 + c];
    float dd1 = dhs[(2*ng+1)*66 + c];
    const float4* Wc = (const float4*)(Wt + c*264 + fg*16);
    #pragma unroll
    for (int q = 0; q < 4; q++){
      float4 w = Wc[q];
      acc0[4*q]   += dd0*w.x; acc0[4*q+1] += dd0*w.y; acc0[4*q+2] += dd0*w.z; acc0[4*q+3] += dd0*w.w;
      acc1[4*q]   += dd1*w.x; acc1[4*q+1] += dd1*w.y; acc1[4*q+2] += dd1*w.z; acc1[4*q+3] += dd1*w.w;
    }
  }
  int n0 = nids[2*ng], n1 = nids[2*ng+1];
  if (n0 >= 0){
    float4* o = (float4*)(d_dB0 + n0*256 + fg*16);
    #pragma unroll
    for (int q = 0; q < 4; q++) o[q] = make_float4(acc0[4*q],acc0[4*q+1],acc0[4*q+2],acc0[4*q+3]);
  }
  if (n1 >= 0){
    float4* o = (float4*)(d_dB0 + n1*256 + fg*16);
    #pragma unroll
    for (int q = 0; q < 4; q++) o[q] = make_float4(acc1[4*q],acc1[4*q+1],acc1[4*q+2],acc1[4*q+3]);
  }
}

// ---------------- energies ----------------
__global__ void k_energy(const float* __restrict__ w_read, const float* __restrict__ ae,
                         const int* __restrict__ batch){
  __shared__ float part[GG];
  int t = threadIdx.x;
  if (t < GG) part[t] = 0.f;
  __syncthreads();
  int n = blockIdx.x*256 + t;
  const float* h = d_h2 + n*64;
  float acc = 0.f;
  #pragma unroll
  for (int c = 0; c < 64; c++) acc += h[c]*w_read[c];
  acc += ae[d_elem[n]];
  atomicAdd(&part[batch[n]], acc);
  __syncthreads();
  if (t < GG) atomicAdd(&d_eng[t], part[t]);
}

__global__ void k_final(float* __restrict__ out){
  int i = blockIdx.x*blockDim.x + threadIdx.x;
  if (i < GG) out[i] = d_eng[i];
  if (i < NN*3) out[GG + i] = -d_gpos[i];
}

// ---------------- launch ----------------
extern "C" void kernel_launch(void* const* d_in, const int* in_sizes, int n_in,
                              void* d_out, int out_size){
  const float* pos    = (const float*)d_in[0];
  const float* attrs  = (const float*)d_in[1];
  const float* shifts = (const float*)d_in[2];
  const float* Wemb   = (const float*)d_in[3];
  const float* aew    = (const float*)d_in[4];
  const float* Wrad   = (const float*)d_in[5];
  const float* Wprod  = (const float*)d_in[6];
  const float* wread  = (const float*)d_in[7];
  const int*   ei     = (const int*)d_in[8];
  const int*   batch  = (const int*)d_in[9];
  float* out = (float*)d_out;

  static bool attr_done = false;
  if (!attr_done){
    cudaFuncSetAttribute(k_gemm_h,   cudaFuncAttributeMaxDynamicSharedMemorySize, GH_SMEM);
    cudaFuncSetAttribute(k_gemm_dB0, cudaFuncAttributeMaxDynamicSharedMemorySize, DB0_SMEM);
    attr_done = true;
  }

  k_prep<<<NN*64/256, 256>>>(attrs);
  k_geom<<<EE/256, 256>>>(pos, shifts, ei);
  k_scan<<<1, 256>>>();
  k_fill_misc<<<256 + NELEM, 256>>>(ei, Wprod, wread);

  k_gather0<<<NN/4, 128>>>(ei, Wemb, Wrad);
  k_gemm_h<<<dim3(NELEM, TILES), 128, GH_SMEM>>>(0, Wprod);
  k_gfused1<<<NN/4, 128>>>(ei, Wemb, Wrad + 512);
  k_gemm_h<<<dim3(NELEM, TILES), 128, GH_SMEM>>>(1, Wprod);
  k_energy<<<NN/256, 256>>>(wread, aew, batch);
  k_gemm_dB0<<<dim3(NELEM, TILES), 256, DB0_SMEM>>>(Wprod);
  k_nbwd0<<<NN/4, 128>>>(ei, Wemb, Wrad);

  k_final<<<(NN*3 + 255)/256, 256>>>(out);
}

// round 5
// speedup vs baseline: 3.3202x; 1.2202x over previous
#include <cuda_runtime.h>

#define NN 8192
#define EE 65536
#define GG 16
#define NELEM 10
#define NBY_PAD (NN + 32*NELEM)
#define NTILES (NBY_PAD/32)

// ---------------- persistent device scratch (zero-init at load; self-cleaned) ----
__device__ float d_vec[EE*3];
__device__ float d_r[EE];
__device__ int   d_act[EE];
__device__ float d_Y[EE*16];
__device__ float d_Rb[EE*8];
__device__ float d_dRb[EE*8];
__device__ float d_A[NN*1024];
__device__ float d_Bf[NN*256];
__device__ float d_h1[NN*64];
__device__ float d_dh1[NN*64];
__device__ float d_dB1e[NELEM*256];
__device__ float d_gpos[NN*3];
__device__ float d_eng[GG];
__device__ int d_elem[NN];
__device__ int d_deg[NN];
__device__ int d_rowptr[NN+1];
__device__ int d_cursor[NN];
__device__ int d_perm[EE];
__device__ int d_elptr[NELEM+1];
__device__ int d_elcur[NELEM];
__device__ int d_nbyel[NBY_PAD];

#define BFLY(p) { _Pragma("unroll") for (int off = 16; off > 0; off >>= 1) p += __shfl_xor_sync(0xffffffffu, p, off); }

__device__ __forceinline__ float dot8(float4 a, float4 b, const float w[8]){
  return a.x*w[0]+a.y*w[1]+a.z*w[2]+a.w*w[3]+b.x*w[4]+b.y*w[5]+b.z*w[6]+b.w*w[7];
}

// ---------------- geometry (edge blocks) + elem decode / nbyel init (node blocks) --
__global__ void k_geom(const float* __restrict__ pos, const float* __restrict__ shifts,
                       const int* __restrict__ ei, const float* __restrict__ attrs){
  if (blockIdx.x >= 256){
    int i = (blockIdx.x - 256)*256 + threadIdx.x;
    if (i < NBY_PAD) d_nbyel[i] = -1;
    if (i < NN){
      int el = 0;
      const float* a = attrs + i*NELEM;
      #pragma unroll
      for (int e = 1; e < NELEM; e++) if (a[e] > 0.5f) el = e;
      d_elem[i] = el;
    }
    return;
  }
  int e = blockIdx.x*256 + threadIdx.x;
  int s = ei[e], n = ei[EE+e];
  float vx = pos[3*n]   - pos[3*s]   + shifts[3*e];
  float vy = pos[3*n+1] - pos[3*s+1] + shifts[3*e+1];
  float vz = pos[3*n+2] - pos[3*s+2] + shifts[3*e+2];
  float r = sqrtf(vx*vx + vy*vy + vz*vz + 1e-9f);
  float u = r*0.2f;
  int act = (u < 1.f);
  d_act[e] = act;
  if (!act) return;
  atomicAdd(&d_deg[n], 1);
  float inv = 1.f/r;
  float x = vx*inv, y = vy*inv, z = vz*inv;
  d_vec[3*e] = x; d_vec[3*e+1] = y; d_vec[3*e+2] = z;
  d_r[e] = inv;
  float x2 = x*x, y2 = y*y, z2 = z*z;
  float* Y = d_Y + e*16;
  Y[0]  = 0.28209479177387814f;
  Y[1]  = 0.4886025119029199f*y;
  Y[2]  = 0.4886025119029199f*z;
  Y[3]  = 0.4886025119029199f*x;
  Y[4]  = 1.0925484305920792f*x*y;
  Y[5]  = 1.0925484305920792f*y*z;
  Y[6]  = 0.31539156525252005f*(3.f*z2 - 1.f);
  Y[7]  = 1.0925484305920792f*x*z;
  Y[8]  = 0.5462742152960396f*(x2 - y2);
  Y[9]  = 0.5900435899266435f*y*(3.f*x2 - y2);
  Y[10] = 2.890611442640554f*x*y*z;
  Y[11] = 0.4570457994644658f*y*(5.f*z2 - 1.f);
  Y[12] = 0.3731763325901154f*z*(5.f*z2 - 3.f);
  Y[13] = 0.4570457994644658f*x*(5.f*z2 - 1.f);
  Y[14] = 1.445305721320277f*z*(x2 - y2);
  Y[15] = 0.5900435899266435f*x*(x2 - 3.f*y2);
  float u2 = u*u; float u4 = u2*u2;
  float omu = 1.f - u;
  float cut  = 1.f + u4*u*(-21.f + u*(35.f - 15.f*u));
  float cutp = -105.f*u4*omu*omu;
  const float pref = 0.6324555320336759f;
  const float PI_F = 3.14159265358979323846f;
  float* R = d_Rb + e*8;
  float* D = d_dRb + e*8;
  #pragma unroll
  for (int b = 1; b <= 8; b++){
    float sp, cp;
    sincospif((float)b*u, &sp, &cp);
    R[b-1] = pref*sp*inv*cut;
    D[b-1] = pref*(((float)b*PI_F*0.2f)*cp*inv - sp*inv*inv)*cut
           + pref*sp*inv*cutp*0.2f;
  }
}

// ---------------- one-block scan: rowptr + 32-padded element offsets ----------------
__global__ void k_scan(){
  __shared__ int wsum[8];
  __shared__ int elbin[NELEM];
  int t = threadIdx.x;          // 256 threads, 32 nodes each
  int lane = t & 31, w = t >> 5;
  if (t < NELEM) elbin[t] = 0;
  __syncthreads();
  int base = t*32;
  int dg[32];
  const int4* dp = (const int4*)(d_deg + base);
  #pragma unroll
  for (int q = 0; q < 8; q++){
    int4 v = dp[q];
    dg[4*q] = v.x; dg[4*q+1] = v.y; dg[4*q+2] = v.z; dg[4*q+3] = v.w;
  }
  int loc[32]; int s = 0;
  #pragma unroll
  for (int i = 0; i < 32; i++){ loc[i] = s; s += dg[i]; }
  for (int i = 0; i < 32; i++) atomicAdd(&elbin[d_elem[base+i]], 1);
  int pref = s;
  #pragma unroll
  for (int off = 1; off < 32; off <<= 1){
    int v = __shfl_up_sync(0xffffffffu, pref, off);
    if (lane >= off) pref += v;
  }
  if (lane == 31) wsum[w] = pref;
  __syncthreads();
  if (t == 0){
    int a = 0;
    #pragma unroll
    for (int k = 0; k < 8; k++){ int tmp = wsum[k]; wsum[k] = a; a += tmp; }
    d_rowptr[NN] = a;
    int b = 0;
    #pragma unroll
    for (int e = 0; e < NELEM; e++){
      d_elptr[e] = b; d_elcur[e] = b;
      b += (elbin[e] + 31) & ~31;     // 32-padded regions
    }
    d_elptr[NELEM] = b;
  }
  __syncthreads();
  int excl = pref - s + wsum[w];
  #pragma unroll
  for (int i = 0; i < 32; i++){
    int v = excl + loc[i];
    d_rowptr[base+i] = v; d_cursor[base+i] = v;
  }
}

// ---------------- fill CSR (active only) + node-by-element + dB1e ----------------
__global__ void k_fill_misc(const int* __restrict__ ei, const float* __restrict__ Wprod,
                            const float* __restrict__ w_read){
  if (blockIdx.x < 256){
    int idx = blockIdx.x*256 + threadIdx.x;
    if (idx < EE && d_act[idx]){
      int p = atomicAdd(&d_cursor[ei[EE+idx]], 1);
      d_perm[p] = idx;
    }
    if (idx < NN){
      int q = atomicAdd(&d_elcur[d_elem[idx]], 1);
      d_nbyel[q] = idx;
    }
  } else {
    __shared__ float wr[64];
    int el = blockIdx.x - 256, f = threadIdx.x;
    if (f < 64) wr[f] = w_read[f];
    __syncthreads();
    const float* W = Wprod + (NELEM + el)*16384 + f*64;
    float acc = 0.f;
    #pragma unroll
    for (int c = 0; c < 64; c++) acc += wr[c]*W[c];
    d_dB1e[el*256 + f] = acc;
  }
}

// ---------------- gather layer 0: A (stored) + B ----------------
__global__ void k_gather0(const int* __restrict__ ei, const float* __restrict__ Wemb,
                          const float* __restrict__ Wrad){
  int n = blockIdx.x*4 + (threadIdx.x >> 5);
  int lane = threadIdx.x & 31;
  float wr0[8], wr1[8];
  #pragma unroll
  for (int b = 0; b < 8; b++){ wr0[b] = Wrad[b*64+lane]; wr1[b] = Wrad[b*64+32+lane]; }
  float a0[16], a1[16];
  #pragma unroll
  for (int i = 0; i < 16; i++){ a0[i] = 0.f; a1[i] = 0.f; }
  int beg = d_rowptr[n], end = d_rowptr[n+1];
  for (int base = beg; base < end; base += 32){
    int j = base + lane;
    int e = 0, els = 0;
    if (j < end){ e = d_perm[j]; els = d_elem[ei[e]]; }
    int m = min(32, end - base);
    for (int k = 0; k < m; k++){
      int ek  = __shfl_sync(0xffffffffu, e, k);
      int elk = __shfl_sync(0xffffffffu, els, k);
      float4 R0 = *(const float4*)(d_Rb + ek*8);
      float4 R1 = *(const float4*)(d_Rb + ek*8 + 4);
      float w0 = dot8(R0, R1, wr0);
      float w1 = dot8(R0, R1, wr1);
      float wh0 = w0 * Wemb[elk*64 + lane];
      float wh1 = w1 * Wemb[elk*64 + 32 + lane];
      const float4* Yp = (const float4*)(d_Y + ek*16);
      #pragma unroll
      for (int q = 0; q < 4; q++){
        float4 y = Yp[q];
        a0[4*q+0] += wh0*y.x; a1[4*q+0] += wh1*y.x;
        a0[4*q+1] += wh0*y.y; a1[4*q+1] += wh1*y.y;
        a0[4*q+2] += wh0*y.z; a1[4*q+2] += wh1*y.z;
        a0[4*q+3] += wh0*y.w; a1[4*q+3] += wh1*y.w;
      }
    }
  }
  float* A = d_A + n*1024;
  #pragma unroll
  for (int lm = 0; lm < 16; lm++){ A[lm*64 + lane] = a0[lm]; A[lm*64 + 32 + lane] = a1[lm]; }
  float b0[4] = {0,0,0,0}, b1[4] = {0,0,0,0};
  #pragma unroll
  for (int lm = 0; lm < 16; lm++){
    int l = (lm == 0) ? 0 : (lm < 4) ? 1 : (lm < 9) ? 2 : 3;
    b0[l] += a0[lm]*a0[lm]; b1[l] += a1[lm]*a1[lm];
  }
  #pragma unroll
  for (int l = 0; l < 4; l++){
    d_Bf[n*256 + l*64 + lane]      = b0[l];
    d_Bf[n*256 + l*64 + 32 + lane] = b1[l];
  }
}

// ---------------- per-edge backward core (Jacobian fused, grads -> gpos) ----------------
template<int LAYER>
__device__ __forceinline__ void edge_bwd_loop(
    int n, int lane, int beg, int end,
    const int* __restrict__ ei, const float* __restrict__ Wemb,
    const float dA0[16], const float dA1[16],
    const float wr0[8], const float wr1[8])
{
  float accx = 0.f, accy = 0.f, accz = 0.f;
  const float c1 = 0.4886025119029199f;
  for (int base = beg; base < end; base += 32){
    int j = base + lane;
    int e = 0, s = 0, els = 0;
    if (j < end){ e = d_perm[j]; s = ei[e]; if (LAYER == 0) els = d_elem[s]; }
    int m = min(32, end - base);
    for (int k = 0; k < m; k++){
      int ek = __shfl_sync(0xffffffffu, e, k);
      int sk = __shfl_sync(0xffffffffu, s, k);
      float4 R0 = *(const float4*)(d_Rb + ek*8);
      float4 R1 = *(const float4*)(d_Rb + ek*8 + 4);
      float4 D0 = *(const float4*)(d_dRb + ek*8);
      float4 D1 = *(const float4*)(d_dRb + ek*8 + 4);
      float w0 = dot8(R0, R1, wr0);
      float w1 = dot8(R0, R1, wr1);
      float hv0, hv1;
      if (LAYER == 1){
        hv0 = d_h1[sk*64 + lane]; hv1 = d_h1[sk*64 + 32 + lane];
      } else {
        int elk = __shfl_sync(0xffffffffu, els, k);
        hv0 = Wemb[elk*64 + lane]; hv1 = Wemb[elk*64 + 32 + lane];
      }
      float wh0 = w0*hv0, wh1 = w1*hv1;
      const float4* Yp = (const float4*)(d_Y + ek*16);
      float Yv[16];
      #pragma unroll
      for (int q = 0; q < 4; q++){
        float4 y = Yp[q];
        Yv[4*q] = y.x; Yv[4*q+1] = y.y; Yv[4*q+2] = y.z; Yv[4*q+3] = y.w;
      }
      float g0 = 0.f, g1 = 0.f;
      #pragma unroll
      for (int lm = 0; lm < 16; lm++){ g0 += dA0[lm]*Yv[lm]; g1 += dA1[lm]*Yv[lm]; }
      float s0 = dot8(D0, D1, wr0);
      float s1 = dot8(D0, D1, wr1);
      float x = d_vec[3*ek], y = d_vec[3*ek+1], z = d_vec[3*ek+2];
      float inv = d_r[ek];
      float x2my2 = x*x - y*y;
      float z2 = z*z;
      float c4x = 1.0925484305920792f*x, c4y = 1.0925484305920792f*y, c4z = 1.0925484305920792f*z;
      float txy = 2.890611442640554f*x*y, txz = 2.890611442640554f*x*z, tyz = 2.890611442640554f*y*z;
      float q13 = 0.4570457994644658f*(5.f*z2 - 1.f);
      float e9  = 3.540261539559861f*x*y;
      float e15 = 1.7701307697799304f*x2my2;
      float pz6 = 1.8923493915151203f*z;
      float q11y = 4.570457994644658f*y*z, q11x = 4.570457994644658f*x*z;
      float p12 = 0.3731763325901154f*(15.f*z2 - 3.f);
      float p14 = 1.445305721320277f*x2my2;
      float px0 = c1*dA0[3] + c4y*dA0[4] + c4z*dA0[7] + c4x*dA0[8] + e9*dA0[9]
                + tyz*dA0[10] + q13*dA0[13] + txz*dA0[14] + e15*dA0[15];
      float py0 = c1*dA0[1] + c4x*dA0[4] + c4z*dA0[5] - c4y*dA0[8] + e15*dA0[9]
                + txz*dA0[10] + q13*dA0[11] - tyz*dA0[14] - e9*dA0[15];
      float pz0 = c1*dA0[2] + c4y*dA0[5] + pz6*dA0[6] + c4x*dA0[7] + txy*dA0[10]
                + q11y*dA0[11] + p12*dA0[12] + q11x*dA0[13] + p14*dA0[14];
      float px1 = c1*dA1[3] + c4y*dA1[4] + c4z*dA1[7] + c4x*dA1[8] + e9*dA1[9]
                + tyz*dA1[10] + q13*dA1[13] + txz*dA1[14] + e15*dA1[15];
      float py1 = c1*dA1[1] + c4x*dA1[4] + c4z*dA1[5] - c4y*dA1[8] + e15*dA1[9]
                + txz*dA1[10] + q13*dA1[11] - tyz*dA1[14] - e9*dA1[15];
      float pz1 = c1*dA1[2] + c4y*dA1[5] + pz6*dA1[6] + c4x*dA1[7] + txy*dA1[10]
                + q11y*dA1[11] + p12*dA1[12] + q11x*dA1[13] + p14*dA1[14];
      float pgx = wh0*px0 + wh1*px1;
      float pgy = wh0*py0 + wh1*py1;
      float pgz = wh0*pz0 + wh1*pz1;
      float prad = g0*hv0*s0 + g1*hv1*s1;
      BFLY(pgx); BFLY(pgy); BFLY(pgz); BFLY(prad);
      if (lane == 0){
        float gdotu = pgx*x + pgy*y + pgz*z;
        float dvx = inv*(pgx - gdotu*x) + prad*x;
        float dvy = inv*(pgy - gdotu*y) + prad*y;
        float dvz = inv*(pgz - gdotu*z) + prad*z;
        accx += dvx; accy += dvy; accz += dvz;
        atomicAdd(&d_gpos[3*sk],   -dvx);
        atomicAdd(&d_gpos[3*sk+1], -dvy);
        atomicAdd(&d_gpos[3*sk+2], -dvz);
      }
      if (LAYER == 1){
        atomicAdd(&d_dh1[sk*64 + lane],      g0*w0);
        atomicAdd(&d_dh1[sk*64 + 32 + lane], g1*w1);
      }
    }
  }
  if (lane == 0 && beg < end){
    atomicAdd(&d_gpos[3*n],   accx);
    atomicAdd(&d_gpos[3*n+1], accy);
    atomicAdd(&d_gpos[3*n+2], accz);
  }
}

// ---------------- fused layer-1 gather (B) + layer-1 backward ----------------
__global__ void k_gfused1(const int* __restrict__ ei, const float* __restrict__ Wemb,
                          const float* __restrict__ Wrad){
  int n = blockIdx.x*4 + (threadIdx.x >> 5);
  int lane = threadIdx.x & 31;
  float wr0[8], wr1[8];
  #pragma unroll
  for (int b = 0; b < 8; b++){ wr0[b] = Wrad[b*64+lane]; wr1[b] = Wrad[b*64+32+lane]; }
  float a0[16], a1[16];
  #pragma unroll
  for (int i = 0; i < 16; i++){ a0[i] = 0.f; a1[i] = 0.f; }
  int beg = d_rowptr[n], end = d_rowptr[n+1];
  for (int base = beg; base < end; base += 32){
    int j = base + lane;
    int e = 0, s = 0;
    if (j < end){ e = d_perm[j]; s = ei[e]; }
    int m = min(32, end - base);
    for (int k = 0; k < m; k++){
      int ek = __shfl_sync(0xffffffffu, e, k);
      int sk = __shfl_sync(0xffffffffu, s, k);
      float4 R0 = *(const float4*)(d_Rb + ek*8);
      float4 R1 = *(const float4*)(d_Rb + ek*8 + 4);
      float w0 = dot8(R0, R1, wr0);
      float w1 = dot8(R0, R1, wr1);
      float wh0 = w0 * d_h1[sk*64 + lane];
      float wh1 = w1 * d_h1[sk*64 + 32 + lane];
      const float4* Yp = (const float4*)(d_Y + ek*16);
      #pragma unroll
      for (int q = 0; q < 4; q++){
        float4 y = Yp[q];
        a0[4*q+0] += wh0*y.x; a1[4*q+0] += wh1*y.x;
        a0[4*q+1] += wh0*y.y; a1[4*q+1] += wh1*y.y;
        a0[4*q+2] += wh0*y.z; a1[4*q+2] += wh1*y.z;
        a0[4*q+3] += wh0*y.w; a1[4*q+3] += wh1*y.w;
      }
    }
  }
  float b0[4] = {0,0,0,0}, b1[4] = {0,0,0,0};
  #pragma unroll
  for (int lm = 0; lm < 16; lm++){
    int l = (lm == 0) ? 0 : (lm < 4) ? 1 : (lm < 9) ? 2 : 3;
    b0[l] += a0[lm]*a0[lm]; b1[l] += a1[lm]*a1[lm];
  }
  #pragma unroll
  for (int l = 0; l < 4; l++){
    d_Bf[n*256 + l*64 + lane]      = b0[l];
    d_Bf[n*256 + l*64 + 32 + lane] = b1[l];
  }
  if (beg == end) return;
  const float* dB = d_dB1e + d_elem[n]*256;
  #pragma unroll
  for (int lm = 0; lm < 16; lm++){
    int l = (lm == 0) ? 0 : (lm < 4) ? 1 : (lm < 9) ? 2 : 3;
    a0[lm] = 2.f*a0[lm]*dB[l*64 + lane];
    a1[lm] = 2.f*a1[lm]*dB[l*64 + 32 + lane];
  }
  edge_bwd_loop<1>(n, lane, beg, end, ei, Wemb, a0, a1, wr0, wr1);
}

// ---------------- element-tiled GEMM: h_out = B @ Wp ; layer1 fuses energy ---------
#define GH_SMEM (16384*4 + 32*257*4 + 128)
template<int LAYER>
__global__ void k_gemm_h(const float* __restrict__ Wprod, const float* __restrict__ w_read,
                         const float* __restrict__ ae, const int* __restrict__ batch){
  extern __shared__ float sm[];
  float* Ws = sm;
  float* Bs = sm + 16384;
  int* nids = (int*)(sm + 16384 + 32*257);
  int base = blockIdx.x*32;
  if (base >= d_elptr[NELEM]) return;
  int el = 0;
  #pragma unroll
  for (int e = 1; e < NELEM; e++) if (d_elptr[e] <= base) el = e;
  int tid = threadIdx.x;   // 128
  const float4* W4 = (const float4*)(Wprod + (LAYER*NELEM + el)*16384);
  float4* Ws4 = (float4*)Ws;
  #pragma unroll
  for (int i = 0; i < 32; i++) Ws4[tid + i*128] = W4[tid + i*128];
  if (tid < 32) nids[tid] = d_nbyel[base + tid];
  __syncthreads();
  for (int i = tid; i < 32*256; i += 128){
    int k = i >> 8, f = i & 255;
    int nn = nids[k];
    Bs[k*257 + f] = (nn >= 0) ? d_Bf[nn*256 + f] : 0.f;
  }
  __syncthreads();
  int ng = tid >> 3, cg = tid & 7;
  const float* B0 = Bs + (2*ng)*257;
  const float* B1 = B0 + 257;
  float acc0[8] = {0,0,0,0,0,0,0,0};
  float acc1[8] = {0,0,0,0,0,0,0,0};
  #pragma unroll 4
  for (int f = 0; f < 256; f++){
    float bb0 = B0[f], bb1 = B1[f];
    float4 w0 = Ws4[f*16 + cg*2];
    float4 w1 = Ws4[f*16 + cg*2 + 1];
    acc0[0] += bb0*w0.x; acc0[1] += bb0*w0.y; acc0[2] += bb0*w0.z; acc0[3] += bb0*w0.w;
    acc0[4] += bb0*w1.x; acc0[5] += bb0*w1.y; acc0[6] += bb0*w1.z; acc0[7] += bb0*w1.w;
    acc1[0] += bb1*w0.x; acc1[1] += bb1*w0.y; acc1[2] += bb1*w0.z; acc1[3] += bb1*w0.w;
    acc1[4] += bb1*w1.x; acc1[5] += bb1*w1.y; acc1[6] += bb1*w1.z; acc1[7] += bb1*w1.w;
  }
  int n0 = nids[2*ng], n1 = nids[2*ng+1];
  if (LAYER == 0){
    if (n0 >= 0){
      float4* o = (float4*)(d_h1 + n0*64 + cg*8);
      o[0] = make_float4(acc0[0],acc0[1],acc0[2],acc0[3]);
      o[1] = make_float4(acc0[4],acc0[5],acc0[6],acc0[7]);
    }
    if (n1 >= 0){
      float4* o = (float4*)(d_h1 + n1*64 + cg*8);
      o[0] = make_float4(acc1[0],acc1[1],acc1[2],acc1[3]);
      o[1] = make_float4(acc1[4],acc1[5],acc1[6],acc1[7]);
    }
  } else {
    // energy epilogue: node_e = h2 . w_read + ae[el], atomic into per-graph energy
    float p0 = 0.f, p1 = 0.f;
    #pragma unroll
    for (int j = 0; j < 8; j++){
      float wv = w_read[cg*8 + j];
      p0 += acc0[j]*wv; p1 += acc1[j]*wv;
    }
    #pragma unroll
    for (int off = 4; off > 0; off >>= 1){
      p0 += __shfl_down_sync(0xffffffffu, p0, off, 8);
      p1 += __shfl_down_sync(0xffffffffu, p1, off, 8);
    }
    if (cg == 0){
      float aev = ae[el];
      if (n0 >= 0) atomicAdd(&d_eng[batch[n0]], p0 + aev);
      if (n1 >= 0) atomicAdd(&d_eng[batch[n1]], p1 + aev);
    }
  }
}

// ---------------- fused: dB0 tile (smem) + layer-0 node backward ----------------
#define BWD0_SMEM (64*264*4 + 32*66*4 + 32*256*4 + 128)
__global__ void k_bwd0(const float* __restrict__ Wprod, const int* __restrict__ ei,
                       const float* __restrict__ Wemb, const float* __restrict__ Wrad){
  extern __shared__ float sm[];
  float* Wt  = sm;                        // [c][f] 64 x 264
  float* dhs = sm + 64*264;               // [node][c] 32 x 66
  float* dBs = sm + 64*264 + 32*66;       // [node][f] 32 x 256
  int* nids  = (int*)(sm + 64*264 + 32*66 + 32*256);
  int base = blockIdx.x*32;
  if (base >= d_elptr[NELEM]) return;
  int el = 0;
  #pragma unroll
  for (int e = 1; e < NELEM; e++) if (d_elptr[e] <= base) el = e;
  int tid = threadIdx.x;   // 256
  const float* W = Wprod + el*16384;
  for (int i = tid; i < 16384; i += 256){
    int f = i >> 6, c = i & 63;
    Wt[c*264 + f] = W[i];
  }
  if (tid < 32) nids[tid] = d_nbyel[base + tid];
  __syncthreads();
  for (int i = tid; i < 32*64; i += 256){
    int k = i >> 6, c = i & 63;
    int nn = nids[k];
    dhs[k*66 + c] = (nn >= 0) ? d_dh1[nn*64 + c] : 0.f;
  }
  __syncthreads();
  {
    int ng = tid >> 4, fg = tid & 15;
    float acc0[16], acc1[16];
    #pragma unroll
    for (int i = 0; i < 16; i++){ acc0[i] = 0.f; acc1[i] = 0.f; }
    #pragma unroll 2
    for (int c = 0; c < 64; c++){
      float dd0 = dhs[(2*ng)*66 + c];
      float dd1 = dhs[(2*ng+1)*66 + c];
      const float4* Wc = (const float4*)(Wt + c*264 + fg*16);
      #pragma unroll
      for (int q = 0; q < 4; q++){
        float4 w = Wc[q];
        acc0[4*q]   += dd0*w.x; acc0[4*q+1] += dd0*w.y; acc0[4*q+2] += dd0*w.z; acc0[4*q+3] += dd0*w.w;
        acc1[4*q]   += dd1*w.x; acc1[4*q+1] += dd1*w.y; acc1[4*q+2] += dd1*w.z; acc1[4*q+3] += dd1*w.w;
      }
    }
    float4* o0 = (float4*)(dBs + (2*ng)*256 + fg*16);
    float4* o1 = (float4*)(dBs + (2*ng+1)*256 + fg*16);
    #pragma unroll
    for (int q = 0; q < 4; q++){
      o0[q] = make_float4(acc0[4*q],acc0[4*q+1],acc0[4*q+2],acc0[4*q+3]);
      o1[q] = make_float4(acc1[4*q],acc1[4*q+1],acc1[4*q+2],acc1[4*q+3]);
    }
  }
  __syncthreads();
  // phase B: 8 warps x 4 nodes, layer-0 edge backward
  int w = tid >> 5, lane = tid & 31;
  float wr0[8], wr1[8];
  #pragma unroll
  for (int b = 0; b < 8; b++){ wr0[b] = Wrad[b*64+lane]; wr1[b] = Wrad[b*64+32+lane]; }
  for (int q = 0; q < 4; q++){
    int nloc = w*4 + q;
    int nn = nids[nloc];
    if (nn < 0) continue;
    int beg = d_rowptr[nn], end = d_rowptr[nn+1];
    if (beg == end) continue;
    const float* dB = dBs + nloc*256;
    const float* A  = d_A + nn*1024;
    float dA0[16], dA1[16];
    #pragma unroll
    for (int lm = 0; lm < 16; lm++){
      int l = (lm == 0) ? 0 : (lm < 4) ? 1 : (lm < 9) ? 2 : 3;
      dA0[lm] = 2.f*A[lm*64 + lane]      * dB[l*64 + lane];
      dA1[lm] = 2.f*A[lm*64 + 32 + lane] * dB[l*64 + 32 + lane];
    }
    edge_bwd_loop<0>(nn, lane, beg, end, ei, Wemb, dA0, dA1, wr0, wr1);
  }
}

// ---------------- final: outputs + self-cleaning for next replay ----------------
__global__ void k_final(float* __restrict__ out){
  int i = blockIdx.x*blockDim.x + threadIdx.x;   // covers NN*64
  if (i < GG){ out[i] = d_eng[i]; d_eng[i] = 0.f; }
  if (i < NN*3){ out[GG + i] = -d_gpos[i]; d_gpos[i] = 0.f; }
  if (i < NN) d_deg[i] = 0;
  d_dh1[i] = 0.f;
}

// ---------------- launch ----------------
extern "C" void kernel_launch(void* const* d_in, const int* in_sizes, int n_in,
                              void* d_out, int out_size){
  const float* pos    = (const float*)d_in[0];
  const float* attrs  = (const float*)d_in[1];
  const float* shifts = (const float*)d_in[2];
  const float* Wemb   = (const float*)d_in[3];
  const float* aew    = (const float*)d_in[4];
  const float* Wrad   = (const float*)d_in[5];
  const float* Wprod  = (const float*)d_in[6];
  const float* wread  = (const float*)d_in[7];
  const int*   ei     = (const int*)d_in[8];
  const int*   batch  = (const int*)d_in[9];
  float* out = (float*)d_out;

  static bool attr_done = false;
  if (!attr_done){
    cudaFuncSetAttribute(k_gemm_h<0>, cudaFuncAttributeMaxDynamicSharedMemorySize, GH_SMEM);
    cudaFuncSetAttribute(k_gemm_h<1>, cudaFuncAttributeMaxDynamicSharedMemorySize, GH_SMEM);
    cudaFuncSetAttribute(k_bwd0,      cudaFuncAttributeMaxDynamicSharedMemorySize, BWD0_SMEM);
    attr_done = true;
  }

  k_geom<<<256 + (NBY_PAD + 255)/256, 256>>>(pos, shifts, ei, attrs);
  k_scan<<<1, 256>>>();
  k_fill_misc<<<256 + NELEM, 256>>>(ei, Wprod, wread);
  k_gather0<<<NN/4, 128>>>(ei, Wemb, Wrad);
  k_gemm_h<0><<<NTILES, 128, GH_SMEM>>>(Wprod, wread, aew, batch);
  k_gfused1<<<NN/4, 128>>>(ei, Wemb, Wrad + 512);
  k_gemm_h<1><<<NTILES, 128, GH_SMEM>>>(Wprod, wread, aew, batch);
  k_bwd0<<<NTILES, 256, BWD0_SMEM>>>(Wprod, ei, Wemb, Wrad);
  k_final<<<NN*64/256, 256>>>(out);
}